// round 12
// baseline (speedup 1.0000x reference)
#include <cuda_runtime.h>
#include <cuda_bf16.h>
#include <cuda_fp16.h>
#include <math.h>
#include <stdint.h>

// Problem constants
#define B_    2
#define N_    2048
#define DIM   1024
#define H_    16
#define HD    64
#define ROWS  (B_ * N_)     // 4096
#define QKV_N (3 * DIM)     // 3072

// ---------------------------------------------------------------------------
// Device scratch (allocation-free)
// ---------------------------------------------------------------------------
__device__ float g_qkv[(size_t)ROWS * QKV_N];
__device__ __half g_in16[(size_t)ROWS * DIM];
__device__ __half g_wq16[(size_t)DIM * QKV_N];      // [K][N]
__device__ __half g_wo16[(size_t)DIM * DIM];        // [K][N]
// head-major [b][h][n][64]
__device__ __nv_bfloat16 g_qh[(size_t)ROWS * DIM], g_ql[(size_t)ROWS * DIM];
__device__ __nv_bfloat16 g_kh[(size_t)ROWS * DIM], g_kl[(size_t)ROWS * DIM];
__device__ __half        g_vh[(size_t)ROWS * DIM];
// attention output row-major [4096][1024], fp16
__device__ __half g_a16[(size_t)ROWS * DIM];
// RoPE cos/sin table [n][i] for i<32
__device__ float2 g_rope[(size_t)N_ * 32];

// ---------------------------------------------------------------------------
// PTX helpers
// ---------------------------------------------------------------------------
__device__ __forceinline__ uint32_t sm32(const void* p) {
    return (uint32_t)__cvta_generic_to_shared(p);
}
__device__ __forceinline__ void ldsm4(uint32_t r[4], uint32_t a) {
    asm volatile("ldmatrix.sync.aligned.m8n8.x4.shared.b16 {%0,%1,%2,%3},[%4];"
                 : "=r"(r[0]), "=r"(r[1]), "=r"(r[2]), "=r"(r[3]) : "r"(a));
}
__device__ __forceinline__ void ldsm4t(uint32_t r[4], uint32_t a) {
    asm volatile("ldmatrix.sync.aligned.m8n8.x4.trans.shared.b16 {%0,%1,%2,%3},[%4];"
                 : "=r"(r[0]), "=r"(r[1]), "=r"(r[2]), "=r"(r[3]) : "r"(a));
}
__device__ __forceinline__ void mma_bf16(float d[4], const uint32_t a[4], const uint32_t b[2]) {
    asm volatile("mma.sync.aligned.m16n8k16.row.col.f32.bf16.bf16.f32 "
                 "{%0,%1,%2,%3},{%4,%5,%6,%7},{%8,%9},{%0,%1,%2,%3};"
                 : "+f"(d[0]), "+f"(d[1]), "+f"(d[2]), "+f"(d[3])
                 : "r"(a[0]), "r"(a[1]), "r"(a[2]), "r"(a[3]), "r"(b[0]), "r"(b[1]));
}
__device__ __forceinline__ void mma_f16(float d[4], const uint32_t a[4], const uint32_t b[2]) {
    asm volatile("mma.sync.aligned.m16n8k16.row.col.f32.f16.f16.f32 "
                 "{%0,%1,%2,%3},{%4,%5,%6,%7},{%8,%9},{%0,%1,%2,%3};"
                 : "+f"(d[0]), "+f"(d[1]), "+f"(d[2]), "+f"(d[3])
                 : "r"(a[0]), "r"(a[1]), "r"(a[2]), "r"(a[3]), "r"(b[0]), "r"(b[1]));
}
__device__ __forceinline__ void cpa16(void* dst, const void* src) {
    asm volatile("cp.async.cg.shared.global [%0],[%1],16;" :: "r"(sm32(dst)), "l"(src));
}
#define CP_COMMIT() asm volatile("cp.async.commit_group;")
#define CP_WAIT(n)  asm volatile("cp.async.wait_group %0;" :: "n"(n))

__device__ __forceinline__ void split2(float x, __nv_bfloat16& h, __nv_bfloat16& l) {
    h = __float2bfloat16_rn(x);
    l = __float2bfloat16_rn(x - __bfloat162float(h));
}
__device__ __forceinline__ uint32_t packh2(float a, float b) {
    __half2 h = __floats2half2_rn(a, b);
    return *(uint32_t*)&h;
}
__device__ __forceinline__ float ex2f(float x) {
    float r;
    asm("ex2.approx.ftz.f32 %0,%1;" : "=f"(r) : "f"(x));
    return r;
}

// ---------------------------------------------------------------------------
// Prepasses
// ---------------------------------------------------------------------------
__global__ void conv_f16(const float* __restrict__ s, __half* __restrict__ d, int n4) {
    int i = blockIdx.x * 256 + threadIdx.x;
    if (i >= n4) return;
    float4 v = ((const float4*)s)[i];
    uint2 u = { packh2(v.x, v.y), packh2(v.z, v.w) };
    ((uint2*)d)[i] = u;
}

__global__ void rope_tab() {
    int idx = blockIdx.x * 256 + threadIdx.x;   // 0..65535
    int n = idx >> 5, i = idx & 31;
    double dinv = exp(-(double)(2 * i) * (9.210340371976184 / 64.0));
    double da = fmod((double)n * dinv, 6.283185307179586476);
    g_rope[idx] = make_float2((float)cos(da), (float)sin(da));
}

// ---------------------------------------------------------------------------
// Single-fp16 GEMM: C[M,N] = A[M,K] @ B[K,N] + bias
// 128x256 tile, BK=64, 4-stage cp.async, 256 threads, warp tile 64x64.
// ---------------------------------------------------------------------------
#define A16EL (128 * 72)           // A stage elements (stride 72)
#define B16EL (64 * 264)           // B stage elements (stride 264, BN=256+8)
#define STG16 (A16EL + B16EL)      // 26112 el = 52224 B
#define GEMM16_SMEM (4 * STG16 * 2)  // 208896 B

__global__ void __launch_bounds__(256, 1) gemm16(
    const __half* __restrict__ A, const __half* __restrict__ B,
    const float* __restrict__ bias, float* __restrict__ C,
    int M, int N, int K)
{
    extern __shared__ __half smh[];

    const int tid = threadIdx.x, lane = tid & 31, warp = tid >> 5;
    const int bm = blockIdx.y * 128, bn = blockIdx.x * 256;
    const int wm = (warp >> 2) * 64, wn = (warp & 3) * 64;

    const int qd = lane >> 3, r8 = lane & 7;
    const int Arow = ((qd & 1) << 3) + r8, Acol = (qd & 2) << 2;

    float acc[4][8][4];
#pragma unroll
    for (int a = 0; a < 4; a++)
#pragma unroll
        for (int b = 0; b < 8; b++)
#pragma unroll
            for (int c = 0; c < 4; c++) acc[a][b][c] = 0.f;

    const int ar = tid >> 3,  ac = (tid & 7) * 8;
    const int br = tid >> 5,  bc = (tid & 31) * 8;
    const int nk = K / 64;

#define STAGE16(kt, s) do {                                                       \
    __half* st = smh + (s) * STG16;                                               \
    _Pragma("unroll")                                                             \
    for (int ii = 0; ii < 4; ii++) {                                              \
        int rr = ar + ii * 32;                                                    \
        cpa16(st + rr * 72 + ac, A + (size_t)(bm + rr) * K + (kt) * 64 + ac);     \
    }                                                                             \
    _Pragma("unroll")                                                             \
    for (int ii = 0; ii < 8; ii++) {                                              \
        int rr = br + ii * 8;                                                     \
        cpa16(st + A16EL + rr * 264 + bc,                                         \
              B + (size_t)((kt) * 64 + rr) * N + bn + bc);                        \
    }                                                                             \
    CP_COMMIT(); } while (0)

    STAGE16(0, 0);
    STAGE16(1, 1);
    STAGE16(2, 2);
    CP_WAIT(2);
    __syncthreads();

    int buf = 0;
    for (int kt = 0; kt < nk; kt++) {
        int bufp = buf + 3 >= 4 ? buf - 1 : buf + 3;
        if (kt + 3 < nk) STAGE16(kt + 3, bufp);

        const __half* st = smh + buf * STG16;
        const __half* Bp = st + A16EL;
#pragma unroll
        for (int ka = 0; ka < 4; ka++) {
            uint32_t af[4][4], bf[4][4];
#pragma unroll
            for (int ma = 0; ma < 4; ma++)
                ldsm4(af[ma], sm32(st + (wm + ma * 16 + Arow) * 72 + ka * 16 + Acol));
#pragma unroll
            for (int nb = 0; nb < 4; nb++)
                ldsm4t(bf[nb], sm32(Bp + (ka * 16 + Arow) * 264 + wn + nb * 16 + Acol));
#pragma unroll
            for (int ma = 0; ma < 4; ma++)
#pragma unroll
                for (int nb = 0; nb < 4; nb++) {
                    mma_f16(acc[ma][2 * nb],     af[ma], bf[nb]);
                    mma_f16(acc[ma][2 * nb + 1], af[ma], bf[nb] + 2);
                }
        }

        if (kt + 3 < nk)      { CP_WAIT(2); }
        else if (kt + 2 < nk) { CP_WAIT(1); }
        else if (kt + 1 < nk) { CP_WAIT(0); }
        __syncthreads();
        buf = buf + 1 == 4 ? 0 : buf + 1;
    }
#undef STAGE16

    const int gr = lane >> 2, tg = lane & 3;
#pragma unroll
    for (int ma = 0; ma < 4; ma++) {
        int row0 = bm + wm + ma * 16 + gr;
#pragma unroll
        for (int na = 0; na < 8; na++) {
            int col = bn + wn + na * 8 + 2 * tg;
            float2 v0 = { acc[ma][na][0] + bias[col], acc[ma][na][1] + bias[col + 1] };
            float2 v1 = { acc[ma][na][2] + bias[col], acc[ma][na][3] + bias[col + 1] };
            *(float2*)&C[(size_t)row0 * N + col]       = v0;
            *(float2*)&C[(size_t)(row0 + 8) * N + col] = v1;
        }
    }
}

// ---------------------------------------------------------------------------
// RMSNorm + RoPE; q/k -> bf16 hi/lo, v -> fp16 single (head-major).
// q carries 0.125 * log2(e) so flash can use exp2.
// ---------------------------------------------------------------------------
__inline__ __device__ float warpsum(float v) {
#pragma unroll
    for (int o = 16; o; o >>= 1) v += __shfl_xor_sync(0xffffffffu, v, o);
    return v;
}

#define QSCALE (0.125f * 1.4426950408889634f)

__global__ void __launch_bounds__(256) rmsnorm_rope(
    const float* __restrict__ qkv,
    const float* __restrict__ q_scale, const float* __restrict__ k_scale)
{
    const int row = blockIdx.x;
    const int b = row >> 11, n = row & (N_ - 1);
    const float* qr = qkv + (size_t)row * QKV_N;
    const float* kr = qr + DIM;
    const float* vr = kr + DIM;
    const int tid = threadIdx.x;

    float sq = 0.f, sk = 0.f;
    for (int c = tid; c < DIM; c += 256) {
        float a = qr[c]; sq += a * a;
        float bb = kr[c]; sk += bb * bb;
    }
    sq = warpsum(sq);
    sk = warpsum(sk);
    __shared__ float sh[16];
    int w = tid >> 5, lane = tid & 31;
    if (lane == 0) { sh[w] = sq; sh[w + 8] = sk; }
    __syncthreads();
    if (tid == 0) {
        float t = 0.f, u = 0.f;
#pragma unroll
        for (int i = 0; i < 8; i++) { t += sh[i]; u += sh[i + 8]; }
        sh[0] = rsqrtf(t * (1.0f / DIM) + 1e-6f);
        sh[8] = rsqrtf(u * (1.0f / DIM) + 1e-6f);
    }
    __syncthreads();
    const float rq = sh[0], rk = sh[8];

    for (int p = tid; p < 512; p += 256) {
        int i = p & 31;
        int h = p >> 5;
        int c1 = h * 64 + i, c2 = c1 + 32;
        float2 cssn = g_rope[n * 32 + i];
        float cs = cssn.x, sn = cssn.y;

        size_t o1 = ((size_t)(b * 16 + h) * N_ + n) * 64 + i;
        size_t o2 = o1 + 32;

        float x1 = qr[c1] * rq * q_scale[c1];
        float x2 = qr[c2] * rq * q_scale[c2];
        float q1 = (x1 * cs - x2 * sn) * QSCALE;
        float q2 = (x2 * cs + x1 * sn) * QSCALE;
        __nv_bfloat16 hh, ll;
        split2(q1, hh, ll); g_qh[o1] = hh; g_ql[o1] = ll;
        split2(q2, hh, ll); g_qh[o2] = hh; g_ql[o2] = ll;

        float y1 = kr[c1] * rk * k_scale[c1];
        float y2 = kr[c2] * rk * k_scale[c2];
        float k1 = y1 * cs - y2 * sn;
        float k2 = y2 * cs + y1 * sn;
        split2(k1, hh, ll); g_kh[o1] = hh; g_kl[o1] = ll;
        split2(k2, hh, ll); g_kh[o2] = hh; g_kl[o2] = ll;
    }
    for (int c = tid; c < DIM; c += 256) {
        int h = c >> 6, d = c & 63;
        size_t o = ((size_t)(b * 16 + h) * N_ + n) * 64 + d;
        g_vh[o] = __float2half_rn(vr[c]);
    }
}

// ---------------------------------------------------------------------------
// Flash attention. 64 queries/block, 128 threads, 2 CTAs/SM, 128-KEY TILES.
// Q staged into the (later overwritten) KV stage-0 area, hoisted to regs.
// No online max. Term-major S (bf16 hi/lo), exp2 softmax, P from acc regs,
// V fp16, output fp16.
// ---------------------------------------------------------------------------
#define QEL   (64 * 72)
#define KEL   (128 * 72)
#define KVST  (3 * KEL)                 // Kh, Kl (bf16), Vh (half) per stage
#define ATT_SMEM (2 * KVST * 2)         // 110592 B
#define NT    (N_ / 128)                // 16 tiles

__global__ void __launch_bounds__(128, 2) flash3()
{
    extern __shared__ __align__(1024) char smc[];
    __nv_bfloat16* sKV = (__nv_bfloat16*)smc;   // 2 stages of KVST

    const int tid = threadIdx.x, lane = tid & 31, warp = tid >> 5;
    const int bhid = blockIdx.x;
    const int b = bhid >> 4, h = bhid & 15;
    const size_t hb = (size_t)bhid * N_ * 64;
    const int q0 = blockIdx.y * 64;

    const int qd = lane >> 3, r8 = lane & 7;
    const int Arow = ((qd & 1) << 3) + r8, Acol = (qd & 2) << 2;
    const int Brow = ((qd & 2) << 2) + r8, Bcol = (qd & 1) << 3;
    const int gr = lane >> 2, tg = lane & 3;

    // ---- Q: stage into scratch (stage-0 area), hoist to regs, release ----
    {
        __nv_bfloat16* sQh = sKV;
        __nv_bfloat16* sQl = sQh + QEL;
#pragma unroll
        for (int i = 0; i < 8; i++) {
            int cid = ((i & 3) << 7) + tid;     // 0..511
            int row = cid >> 3, col = (cid & 7) * 8;
            const __nv_bfloat16* src = (i < 4 ? g_qh : g_ql) + hb + (size_t)(q0 + row) * 64 + col;
            __nv_bfloat16* dst = (i < 4 ? sQh : sQl) + row * 72 + col;
            *(uint4*)dst = *(const uint4*)src;
        }
        __syncthreads();
    }
    uint32_t qhf[4][4], qlf[4][4];
#pragma unroll
    for (int ka = 0; ka < 4; ka++) {
        ldsm4(qhf[ka], sm32(sKV + (warp * 16 + Arow) * 72 + ka * 16 + Acol));
        ldsm4(qlf[ka], sm32(sKV + QEL + (warp * 16 + Arow) * 72 + ka * 16 + Acol));
    }
    __syncthreads();    // all warps done reading Q before KV overwrites

#define FSTAGE(kt, s) do {                                                     \
    __nv_bfloat16* st = sKV + (s) * KVST;                                      \
    _Pragma("unroll")                                                          \
    for (int i8 = 0; i8 < 8; i8++) {                                           \
        int cid = tid + i8 * 128;               /* 0..1023 */                  \
        int rr = cid >> 3, cc = (cid & 7) * 8;                                 \
        size_t go = hb + (size_t)((kt) + rr) * 64 + cc;                        \
        int so = rr * 72 + cc;                                                 \
        cpa16(st + so,       g_kh + go);                                       \
        cpa16(st + KEL + so, g_kl + go);                                       \
        cpa16((__half*)(st + 2 * KEL) + so, g_vh + go);                        \
    }                                                                          \
    CP_COMMIT(); } while (0)

    FSTAGE(0, 0);
    CP_WAIT(0);
    __syncthreads();

    float l0 = 0.f, l1 = 0.f;
    float o[8][4];
#pragma unroll
    for (int a = 0; a < 8; a++)
#pragma unroll
        for (int c = 0; c < 4; c++) o[a][c] = 0.f;

    for (int ti = 0; ti < NT; ti++) {
        const int buf = ti & 1;
        if (ti + 1 < NT) FSTAGE((ti + 1) * 128, buf ^ 1);

        __nv_bfloat16* sKh = sKV + buf * KVST;
        __nv_bfloat16* sKl = sKh + KEL;
        __half*        sVh = (__half*)(sKh + 2 * KEL);

        // S = Q K^T over 128 keys: two 64-key half-tiles, term-major
        float s[16][4];
#pragma unroll
        for (int a = 0; a < 16; a++)
#pragma unroll
            for (int c = 0; c < 4; c++) s[a][c] = 0.f;

#pragma unroll
        for (int hf = 0; hf < 2; hf++) {
            const int ko = hf * 64;      // key row offset in smem
            const int so = hf * 8;       // s[] index offset
#pragma unroll
            for (int ka = 0; ka < 4; ka++) {
                uint32_t bh4[4][4], bl4[4][4];
#pragma unroll
                for (int nb = 0; nb < 4; nb++) {
                    ldsm4(bh4[nb], sm32(sKh + (ko + nb * 16 + Brow) * 72 + ka * 16 + Bcol));
                    ldsm4(bl4[nb], sm32(sKl + (ko + nb * 16 + Brow) * 72 + ka * 16 + Bcol));
                }
#pragma unroll
                for (int nb = 0; nb < 4; nb++) {
                    mma_bf16(s[so + 2 * nb],     qhf[ka], bh4[nb]);
                    mma_bf16(s[so + 2 * nb + 1], qhf[ka], bh4[nb] + 2);
                }
#pragma unroll
                for (int nb = 0; nb < 4; nb++) {
                    mma_bf16(s[so + 2 * nb],     qhf[ka], bl4[nb]);
                    mma_bf16(s[so + 2 * nb + 1], qhf[ka], bl4[nb] + 2);
                }
#pragma unroll
                for (int nb = 0; nb < 4; nb++) {
                    mma_bf16(s[so + 2 * nb],     qlf[ka], bh4[nb]);
                    mma_bf16(s[so + 2 * nb + 1], qlf[ka], bh4[nb] + 2);
                }
            }
        }

        // softmax numerator via exp2, accumulate l
#pragma unroll
        for (int a = 0; a < 16; a++) {
            s[a][0] = ex2f(s[a][0]);
            s[a][1] = ex2f(s[a][1]);
            s[a][2] = ex2f(s[a][2]);
            s[a][3] = ex2f(s[a][3]);
            l0 += s[a][0] + s[a][1];
            l1 += s[a][2] + s[a][3];
        }

        // O += P V over 128 keys: 8 k16-chunks, P from acc regs
#pragma unroll
        for (int ka = 0; ka < 8; ka++) {
            uint32_t pf[4];
            pf[0] = packh2(s[2 * ka][0],     s[2 * ka][1]);
            pf[1] = packh2(s[2 * ka][2],     s[2 * ka][3]);
            pf[2] = packh2(s[2 * ka + 1][0], s[2 * ka + 1][1]);
            pf[3] = packh2(s[2 * ka + 1][2], s[2 * ka + 1][3]);
            uint32_t vh4[4][4];
#pragma unroll
            for (int nb = 0; nb < 4; nb++)
                ldsm4t(vh4[nb], sm32(sVh + (ka * 16 + Arow) * 72 + nb * 16 + Acol));
#pragma unroll
            for (int nb = 0; nb < 4; nb++) {
                mma_f16(o[2 * nb],     pf, vh4[nb]);
                mma_f16(o[2 * nb + 1], pf, vh4[nb] + 2);
            }
        }

        if (ti + 1 < NT) CP_WAIT(0);
        __syncthreads();
    }
#undef FSTAGE

    // reduce l across the 4 threads of each row group
    l0 += __shfl_xor_sync(0xffffffffu, l0, 1);
    l0 += __shfl_xor_sync(0xffffffffu, l0, 2);
    l1 += __shfl_xor_sync(0xffffffffu, l1, 1);
    l1 += __shfl_xor_sync(0xffffffffu, l1, 2);

    const float i0 = 1.f / l0, i1 = 1.f / l1;
    const int r0 = q0 + warp * 16 + gr;
#pragma unroll
    for (int a = 0; a < 8; a++) {
        int col = h * 64 + a * 8 + 2 * tg;
        size_t off = ((size_t)(b * N_ + r0)) * DIM + col;
        *(uint32_t*)&g_a16[off] = packh2(o[a][0] * i0, o[a][1] * i0);
        off = ((size_t)(b * N_ + r0 + 8)) * DIM + col;
        *(uint32_t*)&g_a16[off] = packh2(o[a][2] * i1, o[a][3] * i1);
    }
}

// ---------------------------------------------------------------------------
// Launch
// ---------------------------------------------------------------------------
extern "C" void kernel_launch(void* const* d_in, const int* in_sizes, int n_in,
                              void* d_out, int out_size)
{
    const float* input   = (const float*)d_in[0];
    const float* w_qkv   = (const float*)d_in[1];
    const float* b_qkv   = (const float*)d_in[2];
    const float* q_scale = (const float*)d_in[3];
    const float* k_scale = (const float*)d_in[4];
    const float* w_out   = (const float*)d_in[5];
    const float* b_out   = (const float*)d_in[6];
    float* out = (float*)d_out;

    float* qkv_ptr;
    __half *in16, *wq16, *wo16, *a16;
    cudaGetSymbolAddress((void**)&qkv_ptr, g_qkv);
    cudaGetSymbolAddress((void**)&in16, g_in16);
    cudaGetSymbolAddress((void**)&wq16, g_wq16);
    cudaGetSymbolAddress((void**)&wo16, g_wo16);
    cudaGetSymbolAddress((void**)&a16, g_a16);

    cudaFuncSetAttribute(gemm16, cudaFuncAttributeMaxDynamicSharedMemorySize, GEMM16_SMEM);
    cudaFuncSetAttribute(flash3, cudaFuncAttributeMaxDynamicSharedMemorySize, ATT_SMEM);

    // prepasses
    rope_tab<<<(N_ * 32) / 256, 256>>>();
    {
        int n4 = ROWS * DIM / 4;
        conv_f16<<<(n4 + 255) / 256, 256>>>(input, in16, n4);
        n4 = DIM * QKV_N / 4;
        conv_f16<<<(n4 + 255) / 256, 256>>>(w_qkv, wq16, n4);
        n4 = DIM * DIM / 4;
        conv_f16<<<(n4 + 255) / 256, 256>>>(w_out, wo16, n4);
    }

    {
        dim3 grid(QKV_N / 256, ROWS / 128);
        gemm16<<<grid, 256, GEMM16_SMEM>>>(in16, wq16, b_qkv, qkv_ptr,
                                           ROWS, QKV_N, DIM);
    }

    rmsnorm_rope<<<ROWS, 256>>>(qkv_ptr, q_scale, k_scale);

    {
        dim3 grid(B_ * H_, N_ / 64);
        flash3<<<grid, 128, ATT_SMEM>>>();
    }

    {
        dim3 grid(DIM / 256, ROWS / 128);
        gemm16<<<grid, 256, GEMM16_SMEM>>>(a16, wo16, b_out, out,
                                           ROWS, DIM, DIM);
    }
}

// round 13
// speedup vs baseline: 1.2062x; 1.2062x over previous
#include <cuda_runtime.h>
#include <cuda_bf16.h>
#include <cuda_fp16.h>
#include <math.h>
#include <stdint.h>

// Problem constants
#define B_    2
#define N_    2048
#define DIM   1024
#define H_    16
#define HD    64
#define ROWS  (B_ * N_)     // 4096
#define QKV_N (3 * DIM)     // 3072

// ---------------------------------------------------------------------------
// Device scratch (allocation-free)
// ---------------------------------------------------------------------------
__device__ float g_qkv[(size_t)ROWS * QKV_N];
__device__ __half g_in16[(size_t)ROWS * DIM];
__device__ __half g_wq16[(size_t)DIM * QKV_N];      // [K][N]
__device__ __half g_wo16[(size_t)DIM * DIM];        // [K][N]
// head-major [b][h][n][64]
__device__ __half g_q16[(size_t)ROWS * DIM];                    // q: fp16 single
__device__ __half g_kh16[(size_t)ROWS * DIM], g_kl16[(size_t)ROWS * DIM]; // k: fp16 hi/lo
__device__ __half g_vh[(size_t)ROWS * DIM];
// attention output row-major [4096][1024], fp16
__device__ __half g_a16[(size_t)ROWS * DIM];
// RoPE cos/sin table [n][i] for i<32
__device__ float2 g_rope[(size_t)N_ * 32];

// ---------------------------------------------------------------------------
// PTX helpers
// ---------------------------------------------------------------------------
__device__ __forceinline__ uint32_t sm32(const void* p) {
    return (uint32_t)__cvta_generic_to_shared(p);
}
__device__ __forceinline__ void ldsm4(uint32_t r[4], uint32_t a) {
    asm volatile("ldmatrix.sync.aligned.m8n8.x4.shared.b16 {%0,%1,%2,%3},[%4];"
                 : "=r"(r[0]), "=r"(r[1]), "=r"(r[2]), "=r"(r[3]) : "r"(a));
}
__device__ __forceinline__ void ldsm4t(uint32_t r[4], uint32_t a) {
    asm volatile("ldmatrix.sync.aligned.m8n8.x4.trans.shared.b16 {%0,%1,%2,%3},[%4];"
                 : "=r"(r[0]), "=r"(r[1]), "=r"(r[2]), "=r"(r[3]) : "r"(a));
}
__device__ __forceinline__ void mma_f16(float d[4], const uint32_t a[4], const uint32_t b[2]) {
    asm volatile("mma.sync.aligned.m16n8k16.row.col.f32.f16.f16.f32 "
                 "{%0,%1,%2,%3},{%4,%5,%6,%7},{%8,%9},{%0,%1,%2,%3};"
                 : "+f"(d[0]), "+f"(d[1]), "+f"(d[2]), "+f"(d[3])
                 : "r"(a[0]), "r"(a[1]), "r"(a[2]), "r"(a[3]), "r"(b[0]), "r"(b[1]));
}
__device__ __forceinline__ void cpa16(void* dst, const void* src) {
    asm volatile("cp.async.cg.shared.global [%0],[%1],16;" :: "r"(sm32(dst)), "l"(src));
}
#define CP_COMMIT() asm volatile("cp.async.commit_group;")
#define CP_WAIT(n)  asm volatile("cp.async.wait_group %0;" :: "n"(n))

__device__ __forceinline__ void split2h(float x, __half& h, __half& l) {
    h = __float2half_rn(x);
    l = __float2half_rn(x - __half2float(h));
}
__device__ __forceinline__ uint32_t packh2(float a, float b) {
    __half2 h = __floats2half2_rn(a, b);
    return *(uint32_t*)&h;
}
__device__ __forceinline__ float ex2f(float x) {
    float r;
    asm("ex2.approx.ftz.f32 %0,%1;" : "=f"(r) : "f"(x));
    return r;
}

// ---------------------------------------------------------------------------
// Prepasses
// ---------------------------------------------------------------------------
__global__ void conv_f16(const float* __restrict__ s, __half* __restrict__ d, int n4) {
    int i = blockIdx.x * 256 + threadIdx.x;
    if (i >= n4) return;
    float4 v = ((const float4*)s)[i];
    uint2 u = { packh2(v.x, v.y), packh2(v.z, v.w) };
    ((uint2*)d)[i] = u;
}

__global__ void rope_tab() {
    int idx = blockIdx.x * 256 + threadIdx.x;   // 0..65535
    int n = idx >> 5, i = idx & 31;
    double dinv = exp(-(double)(2 * i) * (9.210340371976184 / 64.0));
    double da = fmod((double)n * dinv, 6.283185307179586476);
    g_rope[idx] = make_float2((float)cos(da), (float)sin(da));
}

// ---------------------------------------------------------------------------
// Single-fp16 GEMM: C[M,N] = A[M,K] @ B[K,N] + bias
// 128x256 tile, BK=64, 3-stage cp.async, 256 threads, warp tile 64x64.
// (R11 configuration — fastest measured.)
// ---------------------------------------------------------------------------
#define A16EL (128 * 72)           // A stage elements (stride 72)
#define B16EL (64 * 264)           // B stage elements (stride 264, BN=256+8)
#define STG16 (A16EL + B16EL)      // 26112 el = 52224 B
#define GEMM16_SMEM (3 * STG16 * 2)  // 156672 B

__global__ void __launch_bounds__(256, 1) gemm16(
    const __half* __restrict__ A, const __half* __restrict__ B,
    const float* __restrict__ bias, float* __restrict__ C,
    int M, int N, int K)
{
    extern __shared__ __half smh[];

    const int tid = threadIdx.x, lane = tid & 31, warp = tid >> 5;
    const int bm = blockIdx.y * 128, bn = blockIdx.x * 256;
    const int wm = (warp >> 2) * 64, wn = (warp & 3) * 64;

    const int qd = lane >> 3, r8 = lane & 7;
    const int Arow = ((qd & 1) << 3) + r8, Acol = (qd & 2) << 2;

    float acc[4][8][4];
#pragma unroll
    for (int a = 0; a < 4; a++)
#pragma unroll
        for (int b = 0; b < 8; b++)
#pragma unroll
            for (int c = 0; c < 4; c++) acc[a][b][c] = 0.f;

    const int ar = tid >> 3,  ac = (tid & 7) * 8;
    const int br = tid >> 5,  bc = (tid & 31) * 8;
    const int nk = K / 64;

#define STAGE16(kt, s) do {                                                       \
    __half* st = smh + (s) * STG16;                                               \
    _Pragma("unroll")                                                             \
    for (int ii = 0; ii < 4; ii++) {                                              \
        int rr = ar + ii * 32;                                                    \
        cpa16(st + rr * 72 + ac, A + (size_t)(bm + rr) * K + (kt) * 64 + ac);     \
    }                                                                             \
    _Pragma("unroll")                                                             \
    for (int ii = 0; ii < 8; ii++) {                                              \
        int rr = br + ii * 8;                                                     \
        cpa16(st + A16EL + rr * 264 + bc,                                         \
              B + (size_t)((kt) * 64 + rr) * N + bn + bc);                        \
    }                                                                             \
    CP_COMMIT(); } while (0)

    STAGE16(0, 0);
    STAGE16(1, 1);
    CP_WAIT(1);
    __syncthreads();

    int buf = 0;
    for (int kt = 0; kt < nk; kt++) {
        int bufn = buf + 1 == 3 ? 0 : buf + 1;
        int bufp = bufn + 1 == 3 ? 0 : bufn + 1;
        if (kt + 2 < nk) STAGE16(kt + 2, bufp);

        const __half* st = smh + buf * STG16;
        const __half* Bp = st + A16EL;
#pragma unroll
        for (int ka = 0; ka < 4; ka++) {
            uint32_t af[4][4], bf[4][4];
#pragma unroll
            for (int ma = 0; ma < 4; ma++)
                ldsm4(af[ma], sm32(st + (wm + ma * 16 + Arow) * 72 + ka * 16 + Acol));
#pragma unroll
            for (int nb = 0; nb < 4; nb++)
                ldsm4t(bf[nb], sm32(Bp + (ka * 16 + Arow) * 264 + wn + nb * 16 + Acol));
#pragma unroll
            for (int ma = 0; ma < 4; ma++)
#pragma unroll
                for (int nb = 0; nb < 4; nb++) {
                    mma_f16(acc[ma][2 * nb],     af[ma], bf[nb]);
                    mma_f16(acc[ma][2 * nb + 1], af[ma], bf[nb] + 2);
                }
        }

        if (kt + 2 < nk) { CP_WAIT(1); } else { CP_WAIT(0); }
        __syncthreads();
        buf = bufn;
    }
#undef STAGE16

    const int gr = lane >> 2, tg = lane & 3;
#pragma unroll
    for (int ma = 0; ma < 4; ma++) {
        int row0 = bm + wm + ma * 16 + gr;
#pragma unroll
        for (int na = 0; na < 8; na++) {
            int col = bn + wn + na * 8 + 2 * tg;
            float2 v0 = { acc[ma][na][0] + bias[col], acc[ma][na][1] + bias[col + 1] };
            float2 v1 = { acc[ma][na][2] + bias[col], acc[ma][na][3] + bias[col + 1] };
            *(float2*)&C[(size_t)row0 * N + col]       = v0;
            *(float2*)&C[(size_t)(row0 + 8) * N + col] = v1;
        }
    }
}

// ---------------------------------------------------------------------------
// RMSNorm + RoPE; q -> fp16 single, k -> fp16 hi/lo, v -> fp16 (head-major).
// q carries 0.125 * log2(e) so flash can use exp2.
// ---------------------------------------------------------------------------
__inline__ __device__ float warpsum(float v) {
#pragma unroll
    for (int o = 16; o; o >>= 1) v += __shfl_xor_sync(0xffffffffu, v, o);
    return v;
}

#define QSCALE (0.125f * 1.4426950408889634f)

__global__ void __launch_bounds__(256) rmsnorm_rope(
    const float* __restrict__ qkv,
    const float* __restrict__ q_scale, const float* __restrict__ k_scale)
{
    const int row = blockIdx.x;
    const int b = row >> 11, n = row & (N_ - 1);
    const float* qr = qkv + (size_t)row * QKV_N;
    const float* kr = qr + DIM;
    const float* vr = kr + DIM;
    const int tid = threadIdx.x;

    float sq = 0.f, sk = 0.f;
    for (int c = tid; c < DIM; c += 256) {
        float a = qr[c]; sq += a * a;
        float bb = kr[c]; sk += bb * bb;
    }
    sq = warpsum(sq);
    sk = warpsum(sk);
    __shared__ float sh[16];
    int w = tid >> 5, lane = tid & 31;
    if (lane == 0) { sh[w] = sq; sh[w + 8] = sk; }
    __syncthreads();
    if (tid == 0) {
        float t = 0.f, u = 0.f;
#pragma unroll
        for (int i = 0; i < 8; i++) { t += sh[i]; u += sh[i + 8]; }
        sh[0] = rsqrtf(t * (1.0f / DIM) + 1e-6f);
        sh[8] = rsqrtf(u * (1.0f / DIM) + 1e-6f);
    }
    __syncthreads();
    const float rq = sh[0], rk = sh[8];

    for (int p = tid; p < 512; p += 256) {
        int i = p & 31;
        int h = p >> 5;
        int c1 = h * 64 + i, c2 = c1 + 32;
        float2 cssn = g_rope[n * 32 + i];
        float cs = cssn.x, sn = cssn.y;

        size_t o1 = ((size_t)(b * 16 + h) * N_ + n) * 64 + i;
        size_t o2 = o1 + 32;

        float x1 = qr[c1] * rq * q_scale[c1];
        float x2 = qr[c2] * rq * q_scale[c2];
        g_q16[o1] = __float2half_rn((x1 * cs - x2 * sn) * QSCALE);
        g_q16[o2] = __float2half_rn((x2 * cs + x1 * sn) * QSCALE);

        float y1 = kr[c1] * rk * k_scale[c1];
        float y2 = kr[c2] * rk * k_scale[c2];
        float k1 = y1 * cs - y2 * sn;
        float k2 = y2 * cs + y1 * sn;
        __half hh, ll;
        split2h(k1, hh, ll); g_kh16[o1] = hh; g_kl16[o1] = ll;
        split2h(k2, hh, ll); g_kh16[o2] = hh; g_kl16[o2] = ll;
    }
    for (int c = tid; c < DIM; c += 256) {
        int h = c >> 6, d = c & 63;
        size_t o = ((size_t)(b * 16 + h) * N_ + n) * 64 + d;
        g_vh[o] = __float2half_rn(vr[c]);
    }
}

// ---------------------------------------------------------------------------
// Flash attention. 64 queries/block, 128 threads, 2 CTAs/SM, 64-key tiles.
// S = q16 * (kh + kl) : 2 fp16 MMAs per quad (q single fp16, k fp16 hi/lo).
// No online max, exp2 softmax, P from acc regs, V fp16, output fp16.
// ---------------------------------------------------------------------------
#define QEL   (64 * 72)
#define KEL   (64 * 72)
#define KVST  (3 * KEL)             // Kh, Kl, Vh (all fp16) per stage
#define ATT_SMEM ((QEL + 2 * KVST) * 2)   // 64512 B

__global__ void __launch_bounds__(128, 2) flash3()
{
    extern __shared__ __align__(1024) char smc[];
    __half* sQ  = (__half*)smc;
    __half* sKV = sQ + QEL;             // 2 stages of KVST elements

    const int tid = threadIdx.x, lane = tid & 31, warp = tid >> 5;
    const int bhid = blockIdx.x;
    const int b = bhid >> 4, h = bhid & 15;
    const size_t hb = (size_t)bhid * N_ * 64;
    const int q0 = blockIdx.y * 64;

#define FSTAGE(kt, s) do {                                                     \
    __half* st = sKV + (s) * KVST;                                             \
    _Pragma("unroll")                                                          \
    for (int i8 = 0; i8 < 4; i8++) {                                           \
        int cid = tid + i8 * 128;                                              \
        int rr = cid >> 3, cc = (cid & 7) * 8;                                 \
        size_t go = hb + (size_t)((kt) + rr) * 64 + cc;                        \
        int so = rr * 72 + cc;                                                 \
        cpa16(st + so,           g_kh16 + go);                                 \
        cpa16(st + KEL + so,     g_kl16 + go);                                 \
        cpa16(st + 2 * KEL + so, g_vh + go);                                   \
    }                                                                          \
    CP_COMMIT(); } while (0)

    FSTAGE(0, 0);

    // stage Q: 512 chunks, 128 threads -> 4 iterations
#pragma unroll
    for (int i = 0; i < 4; i++) {
        int cid = (i << 7) + tid;           // 0..511
        int row = cid >> 3, col = (cid & 7) * 8;
        *(uint4*)(sQ + row * 72 + col) =
            *(const uint4*)(g_q16 + hb + (size_t)(q0 + row) * 64 + col);
    }
    CP_WAIT(0);
    __syncthreads();

    const int qd = lane >> 3, r8 = lane & 7;
    const int Arow = ((qd & 1) << 3) + r8, Acol = (qd & 2) << 2;
    const int Brow = ((qd & 2) << 2) + r8, Bcol = (qd & 1) << 3;
    const int gr = lane >> 2, tg = lane & 3;

    // hoist Q fragments to registers
    uint32_t qf[4][4];
#pragma unroll
    for (int ka = 0; ka < 4; ka++)
        ldsm4(qf[ka], sm32(sQ + (warp * 16 + Arow) * 72 + ka * 16 + Acol));

    float l0 = 0.f, l1 = 0.f;
    float o[8][4];
#pragma unroll
    for (int a = 0; a < 8; a++)
#pragma unroll
        for (int c = 0; c < 4; c++) o[a][c] = 0.f;

    for (int ti = 0; ti < N_ / 64; ti++) {
        const int buf = ti & 1;
        if (ti + 1 < N_ / 64) FSTAGE((ti + 1) * 64, buf ^ 1);

        __half* sKh = sKV + buf * KVST;
        __half* sKl = sKh + KEL;
        __half* sVh = sKh + 2 * KEL;

        // S = q (kh + kl), term-major, acc reuse distance 8
        float s[8][4];
#pragma unroll
        for (int a = 0; a < 8; a++)
#pragma unroll
            for (int c = 0; c < 4; c++) s[a][c] = 0.f;

#pragma unroll
        for (int ka = 0; ka < 4; ka++) {
            uint32_t bh4[4][4], bl4[4][4];
#pragma unroll
            for (int nb = 0; nb < 4; nb++) {
                ldsm4(bh4[nb], sm32(sKh + (nb * 16 + Brow) * 72 + ka * 16 + Bcol));
                ldsm4(bl4[nb], sm32(sKl + (nb * 16 + Brow) * 72 + ka * 16 + Bcol));
            }
#pragma unroll
            for (int nb = 0; nb < 4; nb++) {
                mma_f16(s[2 * nb],     qf[ka], bh4[nb]);
                mma_f16(s[2 * nb + 1], qf[ka], bh4[nb] + 2);
            }
#pragma unroll
            for (int nb = 0; nb < 4; nb++) {
                mma_f16(s[2 * nb],     qf[ka], bl4[nb]);
                mma_f16(s[2 * nb + 1], qf[ka], bl4[nb] + 2);
            }
        }

        // softmax numerator via exp2, accumulate l
#pragma unroll
        for (int a = 0; a < 8; a++) {
            s[a][0] = ex2f(s[a][0]);
            s[a][1] = ex2f(s[a][1]);
            s[a][2] = ex2f(s[a][2]);
            s[a][3] = ex2f(s[a][3]);
            l0 += s[a][0] + s[a][1];
            l1 += s[a][2] + s[a][3];
        }

        // O += P V : P fragments directly from S accumulator regs
#pragma unroll
        for (int ka = 0; ka < 4; ka++) {
            uint32_t pf[4];
            pf[0] = packh2(s[2 * ka][0],     s[2 * ka][1]);
            pf[1] = packh2(s[2 * ka][2],     s[2 * ka][3]);
            pf[2] = packh2(s[2 * ka + 1][0], s[2 * ka + 1][1]);
            pf[3] = packh2(s[2 * ka + 1][2], s[2 * ka + 1][3]);
            uint32_t vh4[4][4];
#pragma unroll
            for (int nb = 0; nb < 4; nb++)
                ldsm4t(vh4[nb], sm32(sVh + (ka * 16 + Arow) * 72 + nb * 16 + Acol));
#pragma unroll
            for (int nb = 0; nb < 4; nb++) {
                mma_f16(o[2 * nb],     pf, vh4[nb]);
                mma_f16(o[2 * nb + 1], pf, vh4[nb] + 2);
            }
        }

        if (ti + 1 < N_ / 64) CP_WAIT(0);
        __syncthreads();
    }
#undef FSTAGE

    // reduce l across the 4 threads of each row group
    l0 += __shfl_xor_sync(0xffffffffu, l0, 1);
    l0 += __shfl_xor_sync(0xffffffffu, l0, 2);
    l1 += __shfl_xor_sync(0xffffffffu, l1, 1);
    l1 += __shfl_xor_sync(0xffffffffu, l1, 2);

    const float i0 = 1.f / l0, i1 = 1.f / l1;
    const int r0 = q0 + warp * 16 + gr;
#pragma unroll
    for (int a = 0; a < 8; a++) {
        int col = h * 64 + a * 8 + 2 * tg;
        size_t off = ((size_t)(b * N_ + r0)) * DIM + col;
        *(uint32_t*)&g_a16[off] = packh2(o[a][0] * i0, o[a][1] * i0);
        off = ((size_t)(b * N_ + r0 + 8)) * DIM + col;
        *(uint32_t*)&g_a16[off] = packh2(o[a][2] * i1, o[a][3] * i1);
    }
}

// ---------------------------------------------------------------------------
// Launch
// ---------------------------------------------------------------------------
extern "C" void kernel_launch(void* const* d_in, const int* in_sizes, int n_in,
                              void* d_out, int out_size)
{
    const float* input   = (const float*)d_in[0];
    const float* w_qkv   = (const float*)d_in[1];
    const float* b_qkv   = (const float*)d_in[2];
    const float* q_scale = (const float*)d_in[3];
    const float* k_scale = (const float*)d_in[4];
    const float* w_out   = (const float*)d_in[5];
    const float* b_out   = (const float*)d_in[6];
    float* out = (float*)d_out;

    float* qkv_ptr;
    __half *in16, *wq16, *wo16, *a16;
    cudaGetSymbolAddress((void**)&qkv_ptr, g_qkv);
    cudaGetSymbolAddress((void**)&in16, g_in16);
    cudaGetSymbolAddress((void**)&wq16, g_wq16);
    cudaGetSymbolAddress((void**)&wo16, g_wo16);
    cudaGetSymbolAddress((void**)&a16, g_a16);

    cudaFuncSetAttribute(gemm16, cudaFuncAttributeMaxDynamicSharedMemorySize, GEMM16_SMEM);
    cudaFuncSetAttribute(flash3, cudaFuncAttributeMaxDynamicSharedMemorySize, ATT_SMEM);

    // prepasses
    rope_tab<<<(N_ * 32) / 256, 256>>>();
    {
        int n4 = ROWS * DIM / 4;
        conv_f16<<<(n4 + 255) / 256, 256>>>(input, in16, n4);
        n4 = DIM * QKV_N / 4;
        conv_f16<<<(n4 + 255) / 256, 256>>>(w_qkv, wq16, n4);
        n4 = DIM * DIM / 4;
        conv_f16<<<(n4 + 255) / 256, 256>>>(w_out, wo16, n4);
    }

    {
        dim3 grid(QKV_N / 256, ROWS / 128);
        gemm16<<<grid, 256, GEMM16_SMEM>>>(in16, wq16, b_qkv, qkv_ptr,
                                           ROWS, QKV_N, DIM);
    }

    rmsnorm_rope<<<ROWS, 256>>>(qkv_ptr, q_scale, k_scale);

    {
        dim3 grid(B_ * H_, N_ / 64);
        flash3<<<grid, 128, ATT_SMEM>>>();
    }

    {
        dim3 grid(DIM / 256, ROWS / 128);
        gemm16<<<grid, 256, GEMM16_SMEM>>>(a16, wo16, b_out, out,
                                           ROWS, DIM, DIM);
    }
}

// round 14
// speedup vs baseline: 1.3966x; 1.1579x over previous
#include <cuda_runtime.h>
#include <cuda_bf16.h>
#include <cuda_fp16.h>
#include <math.h>
#include <stdint.h>

// Problem constants
#define B_    2
#define N_    2048
#define DIM   1024
#define H_    16
#define HD    64
#define ROWS  (B_ * N_)     // 4096
#define QKV_N (3 * DIM)     // 3072

// ---------------------------------------------------------------------------
// Device scratch (allocation-free)
// ---------------------------------------------------------------------------
__device__ float g_qkv[(size_t)ROWS * QKV_N];
__device__ __half g_in16[(size_t)ROWS * DIM];
__device__ __half g_wq16[(size_t)DIM * QKV_N];      // [K][N]
__device__ __half g_wo16[(size_t)DIM * DIM];        // [K][N]
// head-major [b][h][n][64], all fp16 single
__device__ __half g_q16[(size_t)ROWS * DIM];
__device__ __half g_k16[(size_t)ROWS * DIM];
__device__ __half g_vh [(size_t)ROWS * DIM];
// attention output row-major [4096][1024], fp16
__device__ __half g_a16[(size_t)ROWS * DIM];
// RoPE cos/sin table [n][i] for i<32
__device__ float2 g_rope[(size_t)N_ * 32];

// ---------------------------------------------------------------------------
// PTX helpers
// ---------------------------------------------------------------------------
__device__ __forceinline__ uint32_t sm32(const void* p) {
    return (uint32_t)__cvta_generic_to_shared(p);
}
__device__ __forceinline__ void ldsm4(uint32_t r[4], uint32_t a) {
    asm volatile("ldmatrix.sync.aligned.m8n8.x4.shared.b16 {%0,%1,%2,%3},[%4];"
                 : "=r"(r[0]), "=r"(r[1]), "=r"(r[2]), "=r"(r[3]) : "r"(a));
}
__device__ __forceinline__ void ldsm4t(uint32_t r[4], uint32_t a) {
    asm volatile("ldmatrix.sync.aligned.m8n8.x4.trans.shared.b16 {%0,%1,%2,%3},[%4];"
                 : "=r"(r[0]), "=r"(r[1]), "=r"(r[2]), "=r"(r[3]) : "r"(a));
}
__device__ __forceinline__ void mma_f16(float d[4], const uint32_t a[4], const uint32_t b[2]) {
    asm volatile("mma.sync.aligned.m16n8k16.row.col.f32.f16.f16.f32 "
                 "{%0,%1,%2,%3},{%4,%5,%6,%7},{%8,%9},{%0,%1,%2,%3};"
                 : "+f"(d[0]), "+f"(d[1]), "+f"(d[2]), "+f"(d[3])
                 : "r"(a[0]), "r"(a[1]), "r"(a[2]), "r"(a[3]), "r"(b[0]), "r"(b[1]));
}
__device__ __forceinline__ void cpa16(void* dst, const void* src) {
    asm volatile("cp.async.cg.shared.global [%0],[%1],16;" :: "r"(sm32(dst)), "l"(src));
}
#define CP_COMMIT() asm volatile("cp.async.commit_group;")
#define CP_WAIT(n)  asm volatile("cp.async.wait_group %0;" :: "n"(n))

__device__ __forceinline__ uint32_t packh2(float a, float b) {
    __half2 h = __floats2half2_rn(a, b);
    return *(uint32_t*)&h;
}
__device__ __forceinline__ float ex2f(float x) {
    float r;
    asm("ex2.approx.ftz.f32 %0,%1;" : "=f"(r) : "f"(x));
    return r;
}

// ---------------------------------------------------------------------------
// Prepasses
// ---------------------------------------------------------------------------
__global__ void conv_f16(const float* __restrict__ s, __half* __restrict__ d, int n4) {
    int i = blockIdx.x * 256 + threadIdx.x;
    if (i >= n4) return;
    float4 v = ((const float4*)s)[i];
    uint2 u = { packh2(v.x, v.y), packh2(v.z, v.w) };
    ((uint2*)d)[i] = u;
}

__global__ void rope_tab() {
    int idx = blockIdx.x * 256 + threadIdx.x;   // 0..65535
    int n = idx >> 5, i = idx & 31;
    double dinv = exp(-(double)(2 * i) * (9.210340371976184 / 64.0));
    double da = fmod((double)n * dinv, 6.283185307179586476);
    g_rope[idx] = make_float2((float)cos(da), (float)sin(da));
}

// ---------------------------------------------------------------------------
// Single-fp16 GEMM: C[M,N] = A[M,K] @ B[K,N] + bias
// 128x256 tile, BK=64, 3-stage cp.async, 256 threads, warp tile 64x64.
// (R11 configuration — fastest measured.)
// ---------------------------------------------------------------------------
#define A16EL (128 * 72)           // A stage elements (stride 72)
#define B16EL (64 * 264)           // B stage elements (stride 264, BN=256+8)
#define STG16 (A16EL + B16EL)      // 26112 el = 52224 B
#define GEMM16_SMEM (3 * STG16 * 2)  // 156672 B

__global__ void __launch_bounds__(256, 1) gemm16(
    const __half* __restrict__ A, const __half* __restrict__ B,
    const float* __restrict__ bias, float* __restrict__ C,
    int M, int N, int K)
{
    extern __shared__ __half smh[];

    const int tid = threadIdx.x, lane = tid & 31, warp = tid >> 5;
    const int bm = blockIdx.y * 128, bn = blockIdx.x * 256;
    const int wm = (warp >> 2) * 64, wn = (warp & 3) * 64;

    const int qd = lane >> 3, r8 = lane & 7;
    const int Arow = ((qd & 1) << 3) + r8, Acol = (qd & 2) << 2;

    float acc[4][8][4];
#pragma unroll
    for (int a = 0; a < 4; a++)
#pragma unroll
        for (int b = 0; b < 8; b++)
#pragma unroll
            for (int c = 0; c < 4; c++) acc[a][b][c] = 0.f;

    const int ar = tid >> 3,  ac = (tid & 7) * 8;
    const int br = tid >> 5,  bc = (tid & 31) * 8;
    const int nk = K / 64;

#define STAGE16(kt, s) do {                                                       \
    __half* st = smh + (s) * STG16;                                               \
    _Pragma("unroll")                                                             \
    for (int ii = 0; ii < 4; ii++) {                                              \
        int rr = ar + ii * 32;                                                    \
        cpa16(st + rr * 72 + ac, A + (size_t)(bm + rr) * K + (kt) * 64 + ac);     \
    }                                                                             \
    _Pragma("unroll")                                                             \
    for (int ii = 0; ii < 8; ii++) {                                              \
        int rr = br + ii * 8;                                                     \
        cpa16(st + A16EL + rr * 264 + bc,                                         \
              B + (size_t)((kt) * 64 + rr) * N + bn + bc);                        \
    }                                                                             \
    CP_COMMIT(); } while (0)

    STAGE16(0, 0);
    STAGE16(1, 1);
    CP_WAIT(1);
    __syncthreads();

    int buf = 0;
    for (int kt = 0; kt < nk; kt++) {
        int bufn = buf + 1 == 3 ? 0 : buf + 1;
        int bufp = bufn + 1 == 3 ? 0 : bufn + 1;
        if (kt + 2 < nk) STAGE16(kt + 2, bufp);

        const __half* st = smh + buf * STG16;
        const __half* Bp = st + A16EL;
#pragma unroll
        for (int ka = 0; ka < 4; ka++) {
            uint32_t af[4][4], bf[4][4];
#pragma unroll
            for (int ma = 0; ma < 4; ma++)
                ldsm4(af[ma], sm32(st + (wm + ma * 16 + Arow) * 72 + ka * 16 + Acol));
#pragma unroll
            for (int nb = 0; nb < 4; nb++)
                ldsm4t(bf[nb], sm32(Bp + (ka * 16 + Arow) * 264 + wn + nb * 16 + Acol));
#pragma unroll
            for (int ma = 0; ma < 4; ma++)
#pragma unroll
                for (int nb = 0; nb < 4; nb++) {
                    mma_f16(acc[ma][2 * nb],     af[ma], bf[nb]);
                    mma_f16(acc[ma][2 * nb + 1], af[ma], bf[nb] + 2);
                }
        }

        if (kt + 2 < nk) { CP_WAIT(1); } else { CP_WAIT(0); }
        __syncthreads();
        buf = bufn;
    }
#undef STAGE16

    const int gr = lane >> 2, tg = lane & 3;
#pragma unroll
    for (int ma = 0; ma < 4; ma++) {
        int row0 = bm + wm + ma * 16 + gr;
#pragma unroll
        for (int na = 0; na < 8; na++) {
            int col = bn + wn + na * 8 + 2 * tg;
            float2 v0 = { acc[ma][na][0] + bias[col], acc[ma][na][1] + bias[col + 1] };
            float2 v1 = { acc[ma][na][2] + bias[col], acc[ma][na][3] + bias[col + 1] };
            *(float2*)&C[(size_t)row0 * N + col]       = v0;
            *(float2*)&C[(size_t)(row0 + 8) * N + col] = v1;
        }
    }
}

// ---------------------------------------------------------------------------
// RMSNorm + RoPE; q, k, v all -> fp16 single (head-major).
// q carries 0.125 * log2(e) so flash can use exp2.
// ---------------------------------------------------------------------------
__inline__ __device__ float warpsum(float v) {
#pragma unroll
    for (int o = 16; o; o >>= 1) v += __shfl_xor_sync(0xffffffffu, v, o);
    return v;
}

#define QSCALE (0.125f * 1.4426950408889634f)

__global__ void __launch_bounds__(256) rmsnorm_rope(
    const float* __restrict__ qkv,
    const float* __restrict__ q_scale, const float* __restrict__ k_scale)
{
    const int row = blockIdx.x;
    const int b = row >> 11, n = row & (N_ - 1);
    const float* qr = qkv + (size_t)row * QKV_N;
    const float* kr = qr + DIM;
    const float* vr = kr + DIM;
    const int tid = threadIdx.x;

    float sq = 0.f, sk = 0.f;
    for (int c = tid; c < DIM; c += 256) {
        float a = qr[c]; sq += a * a;
        float bb = kr[c]; sk += bb * bb;
    }
    sq = warpsum(sq);
    sk = warpsum(sk);
    __shared__ float sh[16];
    int w = tid >> 5, lane = tid & 31;
    if (lane == 0) { sh[w] = sq; sh[w + 8] = sk; }
    __syncthreads();
    if (tid == 0) {
        float t = 0.f, u = 0.f;
#pragma unroll
        for (int i = 0; i < 8; i++) { t += sh[i]; u += sh[i + 8]; }
        sh[0] = rsqrtf(t * (1.0f / DIM) + 1e-6f);
        sh[8] = rsqrtf(u * (1.0f / DIM) + 1e-6f);
    }
    __syncthreads();
    const float rq = sh[0], rk = sh[8];

    for (int p = tid; p < 512; p += 256) {
        int i = p & 31;
        int h = p >> 5;
        int c1 = h * 64 + i, c2 = c1 + 32;
        float2 cssn = g_rope[n * 32 + i];
        float cs = cssn.x, sn = cssn.y;

        size_t o1 = ((size_t)(b * 16 + h) * N_ + n) * 64 + i;
        size_t o2 = o1 + 32;

        float x1 = qr[c1] * rq * q_scale[c1];
        float x2 = qr[c2] * rq * q_scale[c2];
        g_q16[o1] = __float2half_rn((x1 * cs - x2 * sn) * QSCALE);
        g_q16[o2] = __float2half_rn((x2 * cs + x1 * sn) * QSCALE);

        float y1 = kr[c1] * rk * k_scale[c1];
        float y2 = kr[c2] * rk * k_scale[c2];
        g_k16[o1] = __float2half_rn(y1 * cs - y2 * sn);
        g_k16[o2] = __float2half_rn(y2 * cs + y1 * sn);
    }
    for (int c = tid; c < DIM; c += 256) {
        int h = c >> 6, d = c & 63;
        size_t o = ((size_t)(b * 16 + h) * N_ + n) * 64 + d;
        g_vh[o] = __float2half_rn(vr[c]);
    }
}

// ---------------------------------------------------------------------------
// Flash attention. 64 queries/block, 128 threads, 64-key tiles.
// S = q16 * k16 : single fp16 MMA per quad. No online max, exp2 softmax,
// P from acc regs, V fp16, output fp16. smem 46 KB -> high occupancy.
// ---------------------------------------------------------------------------
#define QEL   (64 * 72)
#define KEL   (64 * 72)
#define KVST  (2 * KEL)             // K, V (fp16) per stage
#define ATT_SMEM ((QEL + 2 * KVST) * 2)   // 46080 B

__global__ void __launch_bounds__(128, 2) flash3()
{
    extern __shared__ __align__(1024) char smc[];
    __half* sQ  = (__half*)smc;
    __half* sKV = sQ + QEL;             // 2 stages of KVST elements

    const int tid = threadIdx.x, lane = tid & 31, warp = tid >> 5;
    const int bhid = blockIdx.x;
    const int b = bhid >> 4, h = bhid & 15;
    const size_t hb = (size_t)bhid * N_ * 64;
    const int q0 = blockIdx.y * 64;

#define FSTAGE(kt, s) do {                                                     \
    __half* st = sKV + (s) * KVST;                                             \
    _Pragma("unroll")                                                          \
    for (int i8 = 0; i8 < 4; i8++) {                                           \
        int cid = tid + i8 * 128;                                              \
        int rr = cid >> 3, cc = (cid & 7) * 8;                                 \
        size_t go = hb + (size_t)((kt) + rr) * 64 + cc;                        \
        int so = rr * 72 + cc;                                                 \
        cpa16(st + so,       g_k16 + go);                                      \
        cpa16(st + KEL + so, g_vh + go);                                       \
    }                                                                          \
    CP_COMMIT(); } while (0)

    FSTAGE(0, 0);

    // stage Q: 512 chunks, 128 threads -> 4 iterations
#pragma unroll
    for (int i = 0; i < 4; i++) {
        int cid = (i << 7) + tid;           // 0..511
        int row = cid >> 3, col = (cid & 7) * 8;
        *(uint4*)(sQ + row * 72 + col) =
            *(const uint4*)(g_q16 + hb + (size_t)(q0 + row) * 64 + col);
    }
    CP_WAIT(0);
    __syncthreads();

    const int qd = lane >> 3, r8 = lane & 7;
    const int Arow = ((qd & 1) << 3) + r8, Acol = (qd & 2) << 2;
    const int Brow = ((qd & 2) << 2) + r8, Bcol = (qd & 1) << 3;
    const int gr = lane >> 2, tg = lane & 3;

    // hoist Q fragments to registers
    uint32_t qf[4][4];
#pragma unroll
    for (int ka = 0; ka < 4; ka++)
        ldsm4(qf[ka], sm32(sQ + (warp * 16 + Arow) * 72 + ka * 16 + Acol));

    float l0 = 0.f, l1 = 0.f;
    float o[8][4];
#pragma unroll
    for (int a = 0; a < 8; a++)
#pragma unroll
        for (int c = 0; c < 4; c++) o[a][c] = 0.f;

    for (int ti = 0; ti < N_ / 64; ti++) {
        const int buf = ti & 1;
        if (ti + 1 < N_ / 64) FSTAGE((ti + 1) * 64, buf ^ 1);

        __half* sKh = sKV + buf * KVST;
        __half* sVh = sKh + KEL;

        // S = q k^T : single-term, acc reuse distance 8
        float s[8][4];
#pragma unroll
        for (int a = 0; a < 8; a++)
#pragma unroll
            for (int c = 0; c < 4; c++) s[a][c] = 0.f;

#pragma unroll
        for (int ka = 0; ka < 4; ka++) {
            uint32_t bh4[4][4];
#pragma unroll
            for (int nb = 0; nb < 4; nb++)
                ldsm4(bh4[nb], sm32(sKh + (nb * 16 + Brow) * 72 + ka * 16 + Bcol));
#pragma unroll
            for (int nb = 0; nb < 4; nb++) {
                mma_f16(s[2 * nb],     qf[ka], bh4[nb]);
                mma_f16(s[2 * nb + 1], qf[ka], bh4[nb] + 2);
            }
        }

        // softmax numerator via exp2, accumulate l
#pragma unroll
        for (int a = 0; a < 8; a++) {
            s[a][0] = ex2f(s[a][0]);
            s[a][1] = ex2f(s[a][1]);
            s[a][2] = ex2f(s[a][2]);
            s[a][3] = ex2f(s[a][3]);
            l0 += s[a][0] + s[a][1];
            l1 += s[a][2] + s[a][3];
        }

        // O += P V : P fragments directly from S accumulator regs
#pragma unroll
        for (int ka = 0; ka < 4; ka++) {
            uint32_t pf[4];
            pf[0] = packh2(s[2 * ka][0],     s[2 * ka][1]);
            pf[1] = packh2(s[2 * ka][2],     s[2 * ka][3]);
            pf[2] = packh2(s[2 * ka + 1][0], s[2 * ka + 1][1]);
            pf[3] = packh2(s[2 * ka + 1][2], s[2 * ka + 1][3]);
            uint32_t vh4[4][4];
#pragma unroll
            for (int nb = 0; nb < 4; nb++)
                ldsm4t(vh4[nb], sm32(sVh + (ka * 16 + Arow) * 72 + nb * 16 + Acol));
#pragma unroll
            for (int nb = 0; nb < 4; nb++) {
                mma_f16(o[2 * nb],     pf, vh4[nb]);
                mma_f16(o[2 * nb + 1], pf, vh4[nb] + 2);
            }
        }

        if (ti + 1 < N_ / 64) CP_WAIT(0);
        __syncthreads();
    }
#undef FSTAGE

    // reduce l across the 4 threads of each row group
    l0 += __shfl_xor_sync(0xffffffffu, l0, 1);
    l0 += __shfl_xor_sync(0xffffffffu, l0, 2);
    l1 += __shfl_xor_sync(0xffffffffu, l1, 1);
    l1 += __shfl_xor_sync(0xffffffffu, l1, 2);

    const float i0 = 1.f / l0, i1 = 1.f / l1;
    const int r0 = q0 + warp * 16 + gr;
#pragma unroll
    for (int a = 0; a < 8; a++) {
        int col = h * 64 + a * 8 + 2 * tg;
        size_t off = ((size_t)(b * N_ + r0)) * DIM + col;
        *(uint32_t*)&g_a16[off] = packh2(o[a][0] * i0, o[a][1] * i0);
        off = ((size_t)(b * N_ + r0 + 8)) * DIM + col;
        *(uint32_t*)&g_a16[off] = packh2(o[a][2] * i1, o[a][3] * i1);
    }
}

// ---------------------------------------------------------------------------
// Launch
// ---------------------------------------------------------------------------
extern "C" void kernel_launch(void* const* d_in, const int* in_sizes, int n_in,
                              void* d_out, int out_size)
{
    const float* input   = (const float*)d_in[0];
    const float* w_qkv   = (const float*)d_in[1];
    const float* b_qkv   = (const float*)d_in[2];
    const float* q_scale = (const float*)d_in[3];
    const float* k_scale = (const float*)d_in[4];
    const float* w_out   = (const float*)d_in[5];
    const float* b_out   = (const float*)d_in[6];
    float* out = (float*)d_out;

    float* qkv_ptr;
    __half *in16, *wq16, *wo16, *a16;
    cudaGetSymbolAddress((void**)&qkv_ptr, g_qkv);
    cudaGetSymbolAddress((void**)&in16, g_in16);
    cudaGetSymbolAddress((void**)&wq16, g_wq16);
    cudaGetSymbolAddress((void**)&wo16, g_wo16);
    cudaGetSymbolAddress((void**)&a16, g_a16);

    cudaFuncSetAttribute(gemm16, cudaFuncAttributeMaxDynamicSharedMemorySize, GEMM16_SMEM);
    cudaFuncSetAttribute(flash3, cudaFuncAttributeMaxDynamicSharedMemorySize, ATT_SMEM);

    // prepasses
    rope_tab<<<(N_ * 32) / 256, 256>>>();
    {
        int n4 = ROWS * DIM / 4;
        conv_f16<<<(n4 + 255) / 256, 256>>>(input, in16, n4);
        n4 = DIM * QKV_N / 4;
        conv_f16<<<(n4 + 255) / 256, 256>>>(w_qkv, wq16, n4);
        n4 = DIM * DIM / 4;
        conv_f16<<<(n4 + 255) / 256, 256>>>(w_out, wo16, n4);
    }

    {
        dim3 grid(QKV_N / 256, ROWS / 128);
        gemm16<<<grid, 256, GEMM16_SMEM>>>(in16, wq16, b_qkv, qkv_ptr,
                                           ROWS, QKV_N, DIM);
    }

    rmsnorm_rope<<<ROWS, 256>>>(qkv_ptr, q_scale, k_scale);

    {
        dim3 grid(B_ * H_, N_ / 64);
        flash3<<<grid, 128, ATT_SMEM>>>();
    }

    {
        dim3 grid(DIM / 256, ROWS / 128);
        gemm16<<<grid, 256, GEMM16_SMEM>>>(a16, wo16, b_out, out,
                                           ROWS, DIM, DIM);
    }
}

// round 15
// speedup vs baseline: 1.4269x; 1.0218x over previous
#include <cuda_runtime.h>
#include <cuda_bf16.h>
#include <cuda_fp16.h>
#include <math.h>
#include <stdint.h>

// Problem constants
#define B_    2
#define N_    2048
#define DIM   1024
#define H_    16
#define HD    64
#define ROWS  (B_ * N_)     // 4096
#define QKV_N (3 * DIM)     // 3072

// ---------------------------------------------------------------------------
// Device scratch (allocation-free)
// ---------------------------------------------------------------------------
__device__ float g_qkv[(size_t)ROWS * QKV_N];
__device__ __half g_in16[(size_t)ROWS * DIM];
__device__ __half g_wq16[(size_t)DIM * QKV_N];      // [K][N]
__device__ __half g_wo16[(size_t)DIM * DIM];        // [K][N]
// head-major [b][h][n][64], all fp16 single
__device__ __half g_q16[(size_t)ROWS * DIM];
__device__ __half g_k16[(size_t)ROWS * DIM];
__device__ __half g_vh [(size_t)ROWS * DIM];
// attention output row-major [4096][1024], fp16
__device__ __half g_a16[(size_t)ROWS * DIM];
// RoPE cos/sin table [n][i] for i<32
__device__ float2 g_rope[(size_t)N_ * 32];

// ---------------------------------------------------------------------------
// PTX helpers
// ---------------------------------------------------------------------------
__device__ __forceinline__ uint32_t sm32(const void* p) {
    return (uint32_t)__cvta_generic_to_shared(p);
}
__device__ __forceinline__ void ldsm4(uint32_t r[4], uint32_t a) {
    asm volatile("ldmatrix.sync.aligned.m8n8.x4.shared.b16 {%0,%1,%2,%3},[%4];"
                 : "=r"(r[0]), "=r"(r[1]), "=r"(r[2]), "=r"(r[3]) : "r"(a));
}
__device__ __forceinline__ void ldsm4t(uint32_t r[4], uint32_t a) {
    asm volatile("ldmatrix.sync.aligned.m8n8.x4.trans.shared.b16 {%0,%1,%2,%3},[%4];"
                 : "=r"(r[0]), "=r"(r[1]), "=r"(r[2]), "=r"(r[3]) : "r"(a));
}
__device__ __forceinline__ void mma_f16(float d[4], const uint32_t a[4], const uint32_t b[2]) {
    asm volatile("mma.sync.aligned.m16n8k16.row.col.f32.f16.f16.f32 "
                 "{%0,%1,%2,%3},{%4,%5,%6,%7},{%8,%9},{%0,%1,%2,%3};"
                 : "+f"(d[0]), "+f"(d[1]), "+f"(d[2]), "+f"(d[3])
                 : "r"(a[0]), "r"(a[1]), "r"(a[2]), "r"(a[3]), "r"(b[0]), "r"(b[1]));
}
__device__ __forceinline__ void cpa16(void* dst, const void* src) {
    asm volatile("cp.async.cg.shared.global [%0],[%1],16;" :: "r"(sm32(dst)), "l"(src));
}
#define CP_COMMIT() asm volatile("cp.async.commit_group;")
#define CP_WAIT(n)  asm volatile("cp.async.wait_group %0;" :: "n"(n))

__device__ __forceinline__ uint32_t packh2(float a, float b) {
    __half2 h = __floats2half2_rn(a, b);
    return *(uint32_t*)&h;
}
__device__ __forceinline__ float ex2f(float x) {
    float r;
    asm("ex2.approx.ftz.f32 %0,%1;" : "=f"(r) : "f"(x));
    return r;
}

// ---------------------------------------------------------------------------
// Fused prepass: all fp32->fp16 conversions + RoPE table in ONE kernel.
// Index ranges (in float4 chunks):
//   [0, C0)            : input  -> g_in16
//   [C0, C0+C1)        : w_qkv  -> g_wq16
//   [C0+C1, C0+C1+C2)  : w_out  -> g_wo16
//   [CT, CT + 65536)   : rope table entries
// ---------------------------------------------------------------------------
#define PC0 (ROWS * DIM / 4)            // 1048576
#define PC1 (DIM * QKV_N / 4)           // 786432
#define PC2 (DIM * DIM / 4)             // 262144
#define PCT (PC0 + PC1 + PC2)           // 2097152
#define PTOT (PCT + N_ * 32)            // + 65536

__device__ __forceinline__ void conv4(const float* __restrict__ s,
                                      __half* __restrict__ d, int i) {
    float4 v = ((const float4*)s)[i];
    uint2 u = { packh2(v.x, v.y), packh2(v.z, v.w) };
    ((uint2*)d)[i] = u;
}

__global__ void prepass(const float* __restrict__ input,
                        const float* __restrict__ w_qkv,
                        const float* __restrict__ w_out) {
    int i = blockIdx.x * 256 + threadIdx.x;
    if (i < PC0) {
        conv4(input, g_in16, i);
    } else if (i < PC0 + PC1) {
        conv4(w_qkv, g_wq16, i - PC0);
    } else if (i < PCT) {
        conv4(w_out, g_wo16, i - PC0 - PC1);
    } else if (i < PTOT) {
        int idx = i - PCT;
        int n = idx >> 5, fi = idx & 31;
        double dinv = exp(-(double)(2 * fi) * (9.210340371976184 / 64.0));
        double da = fmod((double)n * dinv, 6.283185307179586476);
        g_rope[idx] = make_float2((float)cos(da), (float)sin(da));
    }
}

// ---------------------------------------------------------------------------
// Single-fp16 GEMM: C[M,N] = A[M,K] @ B[K,N] + bias
// 128x256 tile, BK=64, 3-stage cp.async, 256 threads, warp tile 64x64.
// (R11 configuration — fastest measured.)
// ---------------------------------------------------------------------------
#define A16EL (128 * 72)           // A stage elements (stride 72)
#define B16EL (64 * 264)           // B stage elements (stride 264, BN=256+8)
#define STG16 (A16EL + B16EL)      // 26112 el = 52224 B
#define GEMM16_SMEM (3 * STG16 * 2)  // 156672 B

__global__ void __launch_bounds__(256, 1) gemm16(
    const __half* __restrict__ A, const __half* __restrict__ B,
    const float* __restrict__ bias, float* __restrict__ C,
    int M, int N, int K)
{
    extern __shared__ __half smh[];

    const int tid = threadIdx.x, lane = tid & 31, warp = tid >> 5;
    const int bm = blockIdx.y * 128, bn = blockIdx.x * 256;
    const int wm = (warp >> 2) * 64, wn = (warp & 3) * 64;

    const int qd = lane >> 3, r8 = lane & 7;
    const int Arow = ((qd & 1) << 3) + r8, Acol = (qd & 2) << 2;

    float acc[4][8][4];
#pragma unroll
    for (int a = 0; a < 4; a++)
#pragma unroll
        for (int b = 0; b < 8; b++)
#pragma unroll
            for (int c = 0; c < 4; c++) acc[a][b][c] = 0.f;

    const int ar = tid >> 3,  ac = (tid & 7) * 8;
    const int br = tid >> 5,  bc = (tid & 31) * 8;
    const int nk = K / 64;

#define STAGE16(kt, s) do {                                                       \
    __half* st = smh + (s) * STG16;                                               \
    _Pragma("unroll")                                                             \
    for (int ii = 0; ii < 4; ii++) {                                              \
        int rr = ar + ii * 32;                                                    \
        cpa16(st + rr * 72 + ac, A + (size_t)(bm + rr) * K + (kt) * 64 + ac);     \
    }                                                                             \
    _Pragma("unroll")                                                             \
    for (int ii = 0; ii < 8; ii++) {                                              \
        int rr = br + ii * 8;                                                     \
        cpa16(st + A16EL + rr * 264 + bc,                                         \
              B + (size_t)((kt) * 64 + rr) * N + bn + bc);                        \
    }                                                                             \
    CP_COMMIT(); } while (0)

    STAGE16(0, 0);
    STAGE16(1, 1);
    CP_WAIT(1);
    __syncthreads();

    int buf = 0;
    for (int kt = 0; kt < nk; kt++) {
        int bufn = buf + 1 == 3 ? 0 : buf + 1;
        int bufp = bufn + 1 == 3 ? 0 : bufn + 1;
        if (kt + 2 < nk) STAGE16(kt + 2, bufp);

        const __half* st = smh + buf * STG16;
        const __half* Bp = st + A16EL;
#pragma unroll
        for (int ka = 0; ka < 4; ka++) {
            uint32_t af[4][4], bf[4][4];
#pragma unroll
            for (int ma = 0; ma < 4; ma++)
                ldsm4(af[ma], sm32(st + (wm + ma * 16 + Arow) * 72 + ka * 16 + Acol));
#pragma unroll
            for (int nb = 0; nb < 4; nb++)
                ldsm4t(bf[nb], sm32(Bp + (ka * 16 + Arow) * 264 + wn + nb * 16 + Acol));
#pragma unroll
            for (int ma = 0; ma < 4; ma++)
#pragma unroll
                for (int nb = 0; nb < 4; nb++) {
                    mma_f16(acc[ma][2 * nb],     af[ma], bf[nb]);
                    mma_f16(acc[ma][2 * nb + 1], af[ma], bf[nb] + 2);
                }
        }

        if (kt + 2 < nk) { CP_WAIT(1); } else { CP_WAIT(0); }
        __syncthreads();
        buf = bufn;
    }
#undef STAGE16

    const int gr = lane >> 2, tg = lane & 3;
#pragma unroll
    for (int ma = 0; ma < 4; ma++) {
        int row0 = bm + wm + ma * 16 + gr;
#pragma unroll
        for (int na = 0; na < 8; na++) {
            int col = bn + wn + na * 8 + 2 * tg;
            float2 v0 = { acc[ma][na][0] + bias[col], acc[ma][na][1] + bias[col + 1] };
            float2 v1 = { acc[ma][na][2] + bias[col], acc[ma][na][3] + bias[col + 1] };
            *(float2*)&C[(size_t)row0 * N + col]       = v0;
            *(float2*)&C[(size_t)(row0 + 8) * N + col] = v1;
        }
    }
}

// ---------------------------------------------------------------------------
// RMSNorm + RoPE; q, k, v all -> fp16 single (head-major).
// q carries 0.125 * log2(e) so flash can use exp2.
// ---------------------------------------------------------------------------
__inline__ __device__ float warpsum(float v) {
#pragma unroll
    for (int o = 16; o; o >>= 1) v += __shfl_xor_sync(0xffffffffu, v, o);
    return v;
}

#define QSCALE (0.125f * 1.4426950408889634f)

__global__ void __launch_bounds__(256) rmsnorm_rope(
    const float* __restrict__ qkv,
    const float* __restrict__ q_scale, const float* __restrict__ k_scale)
{
    const int row = blockIdx.x;
    const int b = row >> 11, n = row & (N_ - 1);
    const float* qr = qkv + (size_t)row * QKV_N;
    const float* kr = qr + DIM;
    const float* vr = kr + DIM;
    const int tid = threadIdx.x;

    float sq = 0.f, sk = 0.f;
    for (int c = tid; c < DIM; c += 256) {
        float a = qr[c]; sq += a * a;
        float bb = kr[c]; sk += bb * bb;
    }
    sq = warpsum(sq);
    sk = warpsum(sk);
    __shared__ float sh[16];
    int w = tid >> 5, lane = tid & 31;
    if (lane == 0) { sh[w] = sq; sh[w + 8] = sk; }
    __syncthreads();
    if (tid == 0) {
        float t = 0.f, u = 0.f;
#pragma unroll
        for (int i = 0; i < 8; i++) { t += sh[i]; u += sh[i + 8]; }
        sh[0] = rsqrtf(t * (1.0f / DIM) + 1e-6f);
        sh[8] = rsqrtf(u * (1.0f / DIM) + 1e-6f);
    }
    __syncthreads();
    const float rq = sh[0], rk = sh[8];

    for (int p = tid; p < 512; p += 256) {
        int i = p & 31;
        int h = p >> 5;
        int c1 = h * 64 + i, c2 = c1 + 32;
        float2 cssn = g_rope[n * 32 + i];
        float cs = cssn.x, sn = cssn.y;

        size_t o1 = ((size_t)(b * 16 + h) * N_ + n) * 64 + i;
        size_t o2 = o1 + 32;

        float x1 = qr[c1] * rq * q_scale[c1];
        float x2 = qr[c2] * rq * q_scale[c2];
        g_q16[o1] = __float2half_rn((x1 * cs - x2 * sn) * QSCALE);
        g_q16[o2] = __float2half_rn((x2 * cs + x1 * sn) * QSCALE);

        float y1 = kr[c1] * rk * k_scale[c1];
        float y2 = kr[c2] * rk * k_scale[c2];
        g_k16[o1] = __float2half_rn(y1 * cs - y2 * sn);
        g_k16[o2] = __float2half_rn(y2 * cs + y1 * sn);
    }
    for (int c = tid; c < DIM; c += 256) {
        int h = c >> 6, d = c & 63;
        size_t o = ((size_t)(b * 16 + h) * N_ + n) * 64 + d;
        g_vh[o] = __float2half_rn(vr[c]);
    }
}

// ---------------------------------------------------------------------------
// Flash attention. 64 queries/block, 128 threads, 3 CTAs/SM, 64-key tiles.
// S = q16 * k16 single fp16 MMA. No online max, exp2 softmax, P from acc
// regs, V fp16, output fp16.
// ---------------------------------------------------------------------------
#define QEL   (64 * 72)
#define KEL   (64 * 72)
#define KVST  (2 * KEL)             // K, V (fp16) per stage
#define ATT_SMEM ((QEL + 2 * KVST) * 2)   // 46080 B

__global__ void __launch_bounds__(128, 3) flash3()
{
    extern __shared__ __align__(1024) char smc[];
    __half* sQ  = (__half*)smc;
    __half* sKV = sQ + QEL;             // 2 stages of KVST elements

    const int tid = threadIdx.x, lane = tid & 31, warp = tid >> 5;
    const int bhid = blockIdx.x;
    const int b = bhid >> 4, h = bhid & 15;
    const size_t hb = (size_t)bhid * N_ * 64;
    const int q0 = blockIdx.y * 64;

#define FSTAGE(kt, s) do {                                                     \
    __half* st = sKV + (s) * KVST;                                             \
    _Pragma("unroll")                                                          \
    for (int i8 = 0; i8 < 4; i8++) {                                           \
        int cid = tid + i8 * 128;                                              \
        int rr = cid >> 3, cc = (cid & 7) * 8;                                 \
        size_t go = hb + (size_t)((kt) + rr) * 64 + cc;                        \
        int so = rr * 72 + cc;                                                 \
        cpa16(st + so,       g_k16 + go);                                      \
        cpa16(st + KEL + so, g_vh + go);                                       \
    }                                                                          \
    CP_COMMIT(); } while (0)

    FSTAGE(0, 0);

    // stage Q: 512 chunks, 128 threads -> 4 iterations
#pragma unroll
    for (int i = 0; i < 4; i++) {
        int cid = (i << 7) + tid;           // 0..511
        int row = cid >> 3, col = (cid & 7) * 8;
        *(uint4*)(sQ + row * 72 + col) =
            *(const uint4*)(g_q16 + hb + (size_t)(q0 + row) * 64 + col);
    }
    CP_WAIT(0);
    __syncthreads();

    const int qd = lane >> 3, r8 = lane & 7;
    const int Arow = ((qd & 1) << 3) + r8, Acol = (qd & 2) << 2;
    const int Brow = ((qd & 2) << 2) + r8, Bcol = (qd & 1) << 3;
    const int gr = lane >> 2, tg = lane & 3;

    // hoist Q fragments to registers
    uint32_t qf[4][4];
#pragma unroll
    for (int ka = 0; ka < 4; ka++)
        ldsm4(qf[ka], sm32(sQ + (warp * 16 + Arow) * 72 + ka * 16 + Acol));

    float l0 = 0.f, l1 = 0.f;
    float o[8][4];
#pragma unroll
    for (int a = 0; a < 8; a++)
#pragma unroll
        for (int c = 0; c < 4; c++) o[a][c] = 0.f;

    for (int ti = 0; ti < N_ / 64; ti++) {
        const int buf = ti & 1;
        if (ti + 1 < N_ / 64) FSTAGE((ti + 1) * 64, buf ^ 1);

        __half* sKh = sKV + buf * KVST;
        __half* sVh = sKh + KEL;

        // S = q k^T : single-term, acc reuse distance 8
        float s[8][4];
#pragma unroll
        for (int a = 0; a < 8; a++)
#pragma unroll
            for (int c = 0; c < 4; c++) s[a][c] = 0.f;

#pragma unroll
        for (int ka = 0; ka < 4; ka++) {
            uint32_t bh4[4][4];
#pragma unroll
            for (int nb = 0; nb < 4; nb++)
                ldsm4(bh4[nb], sm32(sKh + (nb * 16 + Brow) * 72 + ka * 16 + Bcol));
#pragma unroll
            for (int nb = 0; nb < 4; nb++) {
                mma_f16(s[2 * nb],     qf[ka], bh4[nb]);
                mma_f16(s[2 * nb + 1], qf[ka], bh4[nb] + 2);
            }
        }

        // softmax numerator via exp2, accumulate l
#pragma unroll
        for (int a = 0; a < 8; a++) {
            s[a][0] = ex2f(s[a][0]);
            s[a][1] = ex2f(s[a][1]);
            s[a][2] = ex2f(s[a][2]);
            s[a][3] = ex2f(s[a][3]);
            l0 += s[a][0] + s[a][1];
            l1 += s[a][2] + s[a][3];
        }

        // O += P V : P fragments directly from S accumulator regs
#pragma unroll
        for (int ka = 0; ka < 4; ka++) {
            uint32_t pf[4];
            pf[0] = packh2(s[2 * ka][0],     s[2 * ka][1]);
            pf[1] = packh2(s[2 * ka][2],     s[2 * ka][3]);
            pf[2] = packh2(s[2 * ka + 1][0], s[2 * ka + 1][1]);
            pf[3] = packh2(s[2 * ka + 1][2], s[2 * ka + 1][3]);
            uint32_t vh4[4][4];
#pragma unroll
            for (int nb = 0; nb < 4; nb++)
                ldsm4t(vh4[nb], sm32(sVh + (ka * 16 + Arow) * 72 + nb * 16 + Acol));
#pragma unroll
            for (int nb = 0; nb < 4; nb++) {
                mma_f16(o[2 * nb],     pf, vh4[nb]);
                mma_f16(o[2 * nb + 1], pf, vh4[nb] + 2);
            }
        }

        if (ti + 1 < N_ / 64) CP_WAIT(0);
        __syncthreads();
    }
#undef FSTAGE

    // reduce l across the 4 threads of each row group
    l0 += __shfl_xor_sync(0xffffffffu, l0, 1);
    l0 += __shfl_xor_sync(0xffffffffu, l0, 2);
    l1 += __shfl_xor_sync(0xffffffffu, l1, 1);
    l1 += __shfl_xor_sync(0xffffffffu, l1, 2);

    const float i0 = 1.f / l0, i1 = 1.f / l1;
    const int r0 = q0 + warp * 16 + gr;
#pragma unroll
    for (int a = 0; a < 8; a++) {
        int col = h * 64 + a * 8 + 2 * tg;
        size_t off = ((size_t)(b * N_ + r0)) * DIM + col;
        *(uint32_t*)&g_a16[off] = packh2(o[a][0] * i0, o[a][1] * i0);
        off = ((size_t)(b * N_ + r0 + 8)) * DIM + col;
        *(uint32_t*)&g_a16[off] = packh2(o[a][2] * i1, o[a][3] * i1);
    }
}

// ---------------------------------------------------------------------------
// Launch
// ---------------------------------------------------------------------------
extern "C" void kernel_launch(void* const* d_in, const int* in_sizes, int n_in,
                              void* d_out, int out_size)
{
    const float* input   = (const float*)d_in[0];
    const float* w_qkv   = (const float*)d_in[1];
    const float* b_qkv   = (const float*)d_in[2];
    const float* q_scale = (const float*)d_in[3];
    const float* k_scale = (const float*)d_in[4];
    const float* w_out   = (const float*)d_in[5];
    const float* b_out   = (const float*)d_in[6];
    float* out = (float*)d_out;

    float* qkv_ptr;
    __half *in16, *wq16, *wo16, *a16;
    cudaGetSymbolAddress((void**)&qkv_ptr, g_qkv);
    cudaGetSymbolAddress((void**)&in16, g_in16);
    cudaGetSymbolAddress((void**)&wq16, g_wq16);
    cudaGetSymbolAddress((void**)&wo16, g_wo16);
    cudaGetSymbolAddress((void**)&a16, g_a16);

    cudaFuncSetAttribute(gemm16, cudaFuncAttributeMaxDynamicSharedMemorySize, GEMM16_SMEM);
    cudaFuncSetAttribute(flash3, cudaFuncAttributeMaxDynamicSharedMemorySize, ATT_SMEM);

    // fused prepass (conversions + rope table), one launch
    prepass<<<(PTOT + 255) / 256, 256>>>(input, w_qkv, w_out);

    {
        dim3 grid(QKV_N / 256, ROWS / 128);
        gemm16<<<grid, 256, GEMM16_SMEM>>>(in16, wq16, b_qkv, qkv_ptr,
                                           ROWS, QKV_N, DIM);
    }

    rmsnorm_rope<<<ROWS, 256>>>(qkv_ptr, q_scale, k_scale);

    {
        dim3 grid(B_ * H_, N_ / 64);
        flash3<<<grid, 128, ATT_SMEM>>>();
    }

    {
        dim3 grid(DIM / 256, ROWS / 128);
        gemm16<<<grid, 256, GEMM16_SMEM>>>(a16, wo16, b_out, out,
                                           ROWS, DIM, DIM);
    }
}

// round 16
// speedup vs baseline: 1.4366x; 1.0068x over previous
#include <cuda_runtime.h>
#include <cuda_bf16.h>
#include <cuda_fp16.h>
#include <math.h>
#include <stdint.h>

// Problem constants
#define B_    2
#define N_    2048
#define DIM   1024
#define H_    16
#define HD    64
#define ROWS  (B_ * N_)     // 4096
#define QKV_N (3 * DIM)     // 3072

// ---------------------------------------------------------------------------
// Device scratch (allocation-free)
// ---------------------------------------------------------------------------
__device__ float g_qkv[(size_t)ROWS * QKV_N];
__device__ __half g_in16[(size_t)ROWS * DIM];
__device__ __half g_wq16[(size_t)DIM * QKV_N];      // [K][N]
__device__ __half g_wo16[(size_t)DIM * DIM];        // [K][N]
// head-major [b][h][n][64], all fp16 single
__device__ __half g_q16[(size_t)ROWS * DIM];
__device__ __half g_k16[(size_t)ROWS * DIM];
__device__ __half g_vh [(size_t)ROWS * DIM];
// attention output row-major [4096][1024], fp16
__device__ __half g_a16[(size_t)ROWS * DIM];
// RoPE cos/sin table [n][i] for i<32
__device__ float2 g_rope[(size_t)N_ * 32];

// ---------------------------------------------------------------------------
// PTX helpers
// ---------------------------------------------------------------------------
__device__ __forceinline__ uint32_t sm32(const void* p) {
    return (uint32_t)__cvta_generic_to_shared(p);
}
__device__ __forceinline__ void ldsm4(uint32_t r[4], uint32_t a) {
    asm volatile("ldmatrix.sync.aligned.m8n8.x4.shared.b16 {%0,%1,%2,%3},[%4];"
                 : "=r"(r[0]), "=r"(r[1]), "=r"(r[2]), "=r"(r[3]) : "r"(a));
}
__device__ __forceinline__ void ldsm4t(uint32_t r[4], uint32_t a) {
    asm volatile("ldmatrix.sync.aligned.m8n8.x4.trans.shared.b16 {%0,%1,%2,%3},[%4];"
                 : "=r"(r[0]), "=r"(r[1]), "=r"(r[2]), "=r"(r[3]) : "r"(a));
}
__device__ __forceinline__ void mma_f16(float d[4], const uint32_t a[4], const uint32_t b[2]) {
    asm volatile("mma.sync.aligned.m16n8k16.row.col.f32.f16.f16.f32 "
                 "{%0,%1,%2,%3},{%4,%5,%6,%7},{%8,%9},{%0,%1,%2,%3};"
                 : "+f"(d[0]), "+f"(d[1]), "+f"(d[2]), "+f"(d[3])
                 : "r"(a[0]), "r"(a[1]), "r"(a[2]), "r"(a[3]), "r"(b[0]), "r"(b[1]));
}
__device__ __forceinline__ void cpa16(void* dst, const void* src) {
    asm volatile("cp.async.cg.shared.global [%0],[%1],16;" :: "r"(sm32(dst)), "l"(src));
}
#define CP_COMMIT() asm volatile("cp.async.commit_group;")
#define CP_WAIT(n)  asm volatile("cp.async.wait_group %0;" :: "n"(n))

__device__ __forceinline__ uint32_t packh2(float a, float b) {
    __half2 h = __floats2half2_rn(a, b);
    return *(uint32_t*)&h;
}
__device__ __forceinline__ float ex2f(float x) {
    float r;
    asm("ex2.approx.ftz.f32 %0,%1;" : "=f"(r) : "f"(x));
    return r;
}

// ---------------------------------------------------------------------------
// Fused prepass: all fp32->fp16 conversions + RoPE table in ONE kernel.
// Index ranges (in float4 chunks):
//   [0, C0)            : input  -> g_in16
//   [C0, C0+C1)        : w_qkv  -> g_wq16
//   [C0+C1, C0+C1+C2)  : w_out  -> g_wo16
//   [CT, CT + 65536)   : rope table entries
// ---------------------------------------------------------------------------
#define PC0 (ROWS * DIM / 4)            // 1048576
#define PC1 (DIM * QKV_N / 4)           // 786432
#define PC2 (DIM * DIM / 4)             // 262144
#define PCT (PC0 + PC1 + PC2)           // 2097152
#define PTOT (PCT + N_ * 32)            // + 65536

__device__ __forceinline__ void conv4(const float* __restrict__ s,
                                      __half* __restrict__ d, int i) {
    float4 v = ((const float4*)s)[i];
    uint2 u = { packh2(v.x, v.y), packh2(v.z, v.w) };
    ((uint2*)d)[i] = u;
}

__global__ void prepass(const float* __restrict__ input,
                        const float* __restrict__ w_qkv,
                        const float* __restrict__ w_out) {
    int i = blockIdx.x * 256 + threadIdx.x;
    if (i < PC0) {
        conv4(input, g_in16, i);
    } else if (i < PC0 + PC1) {
        conv4(w_qkv, g_wq16, i - PC0);
    } else if (i < PCT) {
        conv4(w_out, g_wo16, i - PC0 - PC1);
    } else if (i < PTOT) {
        int idx = i - PCT;
        int n = idx >> 5, fi = idx & 31;
        double dinv = exp(-(double)(2 * fi) * (9.210340371976184 / 64.0));
        double da = fmod((double)n * dinv, 6.283185307179586476);
        g_rope[idx] = make_float2((float)cos(da), (float)sin(da));
    }
}

// ---------------------------------------------------------------------------
// Single-fp16 GEMM: C[M,N] = A[M,K] @ B[K,N] + bias
// 128x256 tile, BK=64, 3-stage cp.async, 256 threads, warp tile 64x64.
// (R11 configuration — fastest measured.)
// ---------------------------------------------------------------------------
#define A16EL (128 * 72)           // A stage elements (stride 72)
#define B16EL (64 * 264)           // B stage elements (stride 264, BN=256+8)
#define STG16 (A16EL + B16EL)      // 26112 el = 52224 B
#define GEMM16_SMEM (3 * STG16 * 2)  // 156672 B

__global__ void __launch_bounds__(256, 1) gemm16(
    const __half* __restrict__ A, const __half* __restrict__ B,
    const float* __restrict__ bias, float* __restrict__ C,
    int M, int N, int K)
{
    extern __shared__ __half smh[];

    const int tid = threadIdx.x, lane = tid & 31, warp = tid >> 5;
    const int bm = blockIdx.y * 128, bn = blockIdx.x * 256;
    const int wm = (warp >> 2) * 64, wn = (warp & 3) * 64;

    const int qd = lane >> 3, r8 = lane & 7;
    const int Arow = ((qd & 1) << 3) + r8, Acol = (qd & 2) << 2;

    float acc[4][8][4];
#pragma unroll
    for (int a = 0; a < 4; a++)
#pragma unroll
        for (int b = 0; b < 8; b++)
#pragma unroll
            for (int c = 0; c < 4; c++) acc[a][b][c] = 0.f;

    const int ar = tid >> 3,  ac = (tid & 7) * 8;
    const int br = tid >> 5,  bc = (tid & 31) * 8;
    const int nk = K / 64;

#define STAGE16(kt, s) do {                                                       \
    __half* st = smh + (s) * STG16;                                               \
    _Pragma("unroll")                                                             \
    for (int ii = 0; ii < 4; ii++) {                                              \
        int rr = ar + ii * 32;                                                    \
        cpa16(st + rr * 72 + ac, A + (size_t)(bm + rr) * K + (kt) * 64 + ac);     \
    }                                                                             \
    _Pragma("unroll")                                                             \
    for (int ii = 0; ii < 8; ii++) {                                              \
        int rr = br + ii * 8;                                                     \
        cpa16(st + A16EL + rr * 264 + bc,                                         \
              B + (size_t)((kt) * 64 + rr) * N + bn + bc);                        \
    }                                                                             \
    CP_COMMIT(); } while (0)

    STAGE16(0, 0);
    STAGE16(1, 1);
    CP_WAIT(1);
    __syncthreads();

    int buf = 0;
    for (int kt = 0; kt < nk; kt++) {
        int bufn = buf + 1 == 3 ? 0 : buf + 1;
        int bufp = bufn + 1 == 3 ? 0 : bufn + 1;
        if (kt + 2 < nk) STAGE16(kt + 2, bufp);

        const __half* st = smh + buf * STG16;
        const __half* Bp = st + A16EL;
#pragma unroll
        for (int ka = 0; ka < 4; ka++) {
            uint32_t af[4][4], bf[4][4];
#pragma unroll
            for (int ma = 0; ma < 4; ma++)
                ldsm4(af[ma], sm32(st + (wm + ma * 16 + Arow) * 72 + ka * 16 + Acol));
#pragma unroll
            for (int nb = 0; nb < 4; nb++)
                ldsm4t(bf[nb], sm32(Bp + (ka * 16 + Arow) * 264 + wn + nb * 16 + Acol));
#pragma unroll
            for (int ma = 0; ma < 4; ma++)
#pragma unroll
                for (int nb = 0; nb < 4; nb++) {
                    mma_f16(acc[ma][2 * nb],     af[ma], bf[nb]);
                    mma_f16(acc[ma][2 * nb + 1], af[ma], bf[nb] + 2);
                }
        }

        if (kt + 2 < nk) { CP_WAIT(1); } else { CP_WAIT(0); }
        __syncthreads();
        buf = bufn;
    }
#undef STAGE16

    const int gr = lane >> 2, tg = lane & 3;
#pragma unroll
    for (int ma = 0; ma < 4; ma++) {
        int row0 = bm + wm + ma * 16 + gr;
#pragma unroll
        for (int na = 0; na < 8; na++) {
            int col = bn + wn + na * 8 + 2 * tg;
            float2 v0 = { acc[ma][na][0] + bias[col], acc[ma][na][1] + bias[col + 1] };
            float2 v1 = { acc[ma][na][2] + bias[col], acc[ma][na][3] + bias[col + 1] };
            *(float2*)&C[(size_t)row0 * N + col]       = v0;
            *(float2*)&C[(size_t)(row0 + 8) * N + col] = v1;
        }
    }
}

// ---------------------------------------------------------------------------
// RMSNorm + RoPE; q, k, v all -> fp16 single (head-major).
// q carries 0.125 * log2(e) so flash can use exp2.
// ---------------------------------------------------------------------------
__inline__ __device__ float warpsum(float v) {
#pragma unroll
    for (int o = 16; o; o >>= 1) v += __shfl_xor_sync(0xffffffffu, v, o);
    return v;
}

#define QSCALE (0.125f * 1.4426950408889634f)

__global__ void __launch_bounds__(256) rmsnorm_rope(
    const float* __restrict__ qkv,
    const float* __restrict__ q_scale, const float* __restrict__ k_scale)
{
    const int row = blockIdx.x;
    const int b = row >> 11, n = row & (N_ - 1);
    const float* qr = qkv + (size_t)row * QKV_N;
    const float* kr = qr + DIM;
    const float* vr = kr + DIM;
    const int tid = threadIdx.x;

    float sq = 0.f, sk = 0.f;
    for (int c = tid; c < DIM; c += 256) {
        float a = qr[c]; sq += a * a;
        float bb = kr[c]; sk += bb * bb;
    }
    sq = warpsum(sq);
    sk = warpsum(sk);
    __shared__ float sh[16];
    int w = tid >> 5, lane = tid & 31;
    if (lane == 0) { sh[w] = sq; sh[w + 8] = sk; }
    __syncthreads();
    if (tid == 0) {
        float t = 0.f, u = 0.f;
#pragma unroll
        for (int i = 0; i < 8; i++) { t += sh[i]; u += sh[i + 8]; }
        sh[0] = rsqrtf(t * (1.0f / DIM) + 1e-6f);
        sh[8] = rsqrtf(u * (1.0f / DIM) + 1e-6f);
    }
    __syncthreads();
    const float rq = sh[0], rk = sh[8];

    for (int p = tid; p < 512; p += 256) {
        int i = p & 31;
        int h = p >> 5;
        int c1 = h * 64 + i, c2 = c1 + 32;
        float2 cssn = g_rope[n * 32 + i];
        float cs = cssn.x, sn = cssn.y;

        size_t o1 = ((size_t)(b * 16 + h) * N_ + n) * 64 + i;
        size_t o2 = o1 + 32;

        float x1 = qr[c1] * rq * q_scale[c1];
        float x2 = qr[c2] * rq * q_scale[c2];
        g_q16[o1] = __float2half_rn((x1 * cs - x2 * sn) * QSCALE);
        g_q16[o2] = __float2half_rn((x2 * cs + x1 * sn) * QSCALE);

        float y1 = kr[c1] * rk * k_scale[c1];
        float y2 = kr[c2] * rk * k_scale[c2];
        g_k16[o1] = __float2half_rn(y1 * cs - y2 * sn);
        g_k16[o2] = __float2half_rn(y2 * cs + y1 * sn);
    }
    for (int c = tid; c < DIM; c += 256) {
        int h = c >> 6, d = c & 63;
        size_t o = ((size_t)(b * 16 + h) * N_ + n) * 64 + d;
        g_vh[o] = __float2half_rn(vr[c]);
    }
}

// ---------------------------------------------------------------------------
// Flash attention. 64 queries/block, 128 threads, 3 CTAs/SM, 64-key tiles.
// S = q16 * k16 single fp16 MMA. No online max, exp2 softmax, P from acc
// regs, V fp16, output fp16.
// ---------------------------------------------------------------------------
#define QEL   (64 * 72)
#define KEL   (64 * 72)
#define KVST  (2 * KEL)             // K, V (fp16) per stage
#define ATT_SMEM ((QEL + 2 * KVST) * 2)   // 46080 B

__global__ void __launch_bounds__(128, 3) flash3()
{
    extern __shared__ __align__(1024) char smc[];
    __half* sQ  = (__half*)smc;
    __half* sKV = sQ + QEL;             // 2 stages of KVST elements

    const int tid = threadIdx.x, lane = tid & 31, warp = tid >> 5;
    const int bhid = blockIdx.x;
    const int b = bhid >> 4, h = bhid & 15;
    const size_t hb = (size_t)bhid * N_ * 64;
    const int q0 = blockIdx.y * 64;

#define FSTAGE(kt, s) do {                                                     \
    __half* st = sKV + (s) * KVST;                                             \
    _Pragma("unroll")                                                          \
    for (int i8 = 0; i8 < 4; i8++) {                                           \
        int cid = tid + i8 * 128;                                              \
        int rr = cid >> 3, cc = (cid & 7) * 8;                                 \
        size_t go = hb + (size_t)((kt) + rr) * 64 + cc;                        \
        int so = rr * 72 + cc;                                                 \
        cpa16(st + so,       g_k16 + go);                                      \
        cpa16(st + KEL + so, g_vh + go);                                       \
    }                                                                          \
    CP_COMMIT(); } while (0)

    FSTAGE(0, 0);

    // stage Q: 512 chunks, 128 threads -> 4 iterations
#pragma unroll
    for (int i = 0; i < 4; i++) {
        int cid = (i << 7) + tid;           // 0..511
        int row = cid >> 3, col = (cid & 7) * 8;
        *(uint4*)(sQ + row * 72 + col) =
            *(const uint4*)(g_q16 + hb + (size_t)(q0 + row) * 64 + col);
    }
    CP_WAIT(0);
    __syncthreads();

    const int qd = lane >> 3, r8 = lane & 7;
    const int Arow = ((qd & 1) << 3) + r8, Acol = (qd & 2) << 2;
    const int Brow = ((qd & 2) << 2) + r8, Bcol = (qd & 1) << 3;
    const int gr = lane >> 2, tg = lane & 3;

    // hoist Q fragments to registers
    uint32_t qf[4][4];
#pragma unroll
    for (int ka = 0; ka < 4; ka++)
        ldsm4(qf[ka], sm32(sQ + (warp * 16 + Arow) * 72 + ka * 16 + Acol));

    float l0 = 0.f, l1 = 0.f;
    float o[8][4];
#pragma unroll
    for (int a = 0; a < 8; a++)
#pragma unroll
        for (int c = 0; c < 4; c++) o[a][c] = 0.f;

    for (int ti = 0; ti < N_ / 64; ti++) {
        const int buf = ti & 1;
        if (ti + 1 < N_ / 64) FSTAGE((ti + 1) * 64, buf ^ 1);

        __half* sKh = sKV + buf * KVST;
        __half* sVh = sKh + KEL;

        // S = q k^T : single-term, acc reuse distance 8
        float s[8][4];
#pragma unroll
        for (int a = 0; a < 8; a++)
#pragma unroll
            for (int c = 0; c < 4; c++) s[a][c] = 0.f;

#pragma unroll
        for (int ka = 0; ka < 4; ka++) {
            uint32_t bh4[4][4];
#pragma unroll
            for (int nb = 0; nb < 4; nb++)
                ldsm4(bh4[nb], sm32(sKh + (nb * 16 + Brow) * 72 + ka * 16 + Bcol));
#pragma unroll
            for (int nb = 0; nb < 4; nb++) {
                mma_f16(s[2 * nb],     qf[ka], bh4[nb]);
                mma_f16(s[2 * nb + 1], qf[ka], bh4[nb] + 2);
            }
        }

        // softmax numerator via exp2, accumulate l
#pragma unroll
        for (int a = 0; a < 8; a++) {
            s[a][0] = ex2f(s[a][0]);
            s[a][1] = ex2f(s[a][1]);
            s[a][2] = ex2f(s[a][2]);
            s[a][3] = ex2f(s[a][3]);
            l0 += s[a][0] + s[a][1];
            l1 += s[a][2] + s[a][3];
        }

        // O += P V : P fragments directly from S accumulator regs
#pragma unroll
        for (int ka = 0; ka < 4; ka++) {
            uint32_t pf[4];
            pf[0] = packh2(s[2 * ka][0],     s[2 * ka][1]);
            pf[1] = packh2(s[2 * ka][2],     s[2 * ka][3]);
            pf[2] = packh2(s[2 * ka + 1][0], s[2 * ka + 1][1]);
            pf[3] = packh2(s[2 * ka + 1][2], s[2 * ka + 1][3]);
            uint32_t vh4[4][4];
#pragma unroll
            for (int nb = 0; nb < 4; nb++)
                ldsm4t(vh4[nb], sm32(sVh + (ka * 16 + Arow) * 72 + nb * 16 + Acol));
#pragma unroll
            for (int nb = 0; nb < 4; nb++) {
                mma_f16(o[2 * nb],     pf, vh4[nb]);
                mma_f16(o[2 * nb + 1], pf, vh4[nb] + 2);
            }
        }

        if (ti + 1 < N_ / 64) CP_WAIT(0);
        __syncthreads();
    }
#undef FSTAGE

    // reduce l across the 4 threads of each row group
    l0 += __shfl_xor_sync(0xffffffffu, l0, 1);
    l0 += __shfl_xor_sync(0xffffffffu, l0, 2);
    l1 += __shfl_xor_sync(0xffffffffu, l1, 1);
    l1 += __shfl_xor_sync(0xffffffffu, l1, 2);

    const float i0 = 1.f / l0, i1 = 1.f / l1;
    const int r0 = q0 + warp * 16 + gr;
#pragma unroll
    for (int a = 0; a < 8; a++) {
        int col = h * 64 + a * 8 + 2 * tg;
        size_t off = ((size_t)(b * N_ + r0)) * DIM + col;
        *(uint32_t*)&g_a16[off] = packh2(o[a][0] * i0, o[a][1] * i0);
        off = ((size_t)(b * N_ + r0 + 8)) * DIM + col;
        *(uint32_t*)&g_a16[off] = packh2(o[a][2] * i1, o[a][3] * i1);
    }
}

// ---------------------------------------------------------------------------
// Launch
// ---------------------------------------------------------------------------
extern "C" void kernel_launch(void* const* d_in, const int* in_sizes, int n_in,
                              void* d_out, int out_size)
{
    const float* input   = (const float*)d_in[0];
    const float* w_qkv   = (const float*)d_in[1];
    const float* b_qkv   = (const float*)d_in[2];
    const float* q_scale = (const float*)d_in[3];
    const float* k_scale = (const float*)d_in[4];
    const float* w_out   = (const float*)d_in[5];
    const float* b_out   = (const float*)d_in[6];
    float* out = (float*)d_out;

    float* qkv_ptr;
    __half *in16, *wq16, *wo16, *a16;
    cudaGetSymbolAddress((void**)&qkv_ptr, g_qkv);
    cudaGetSymbolAddress((void**)&in16, g_in16);
    cudaGetSymbolAddress((void**)&wq16, g_wq16);
    cudaGetSymbolAddress((void**)&wo16, g_wo16);
    cudaGetSymbolAddress((void**)&a16, g_a16);

    cudaFuncSetAttribute(gemm16, cudaFuncAttributeMaxDynamicSharedMemorySize, GEMM16_SMEM);
    cudaFuncSetAttribute(flash3, cudaFuncAttributeMaxDynamicSharedMemorySize, ATT_SMEM);

    // fused prepass (conversions + rope table), one launch
    prepass<<<(PTOT + 255) / 256, 256>>>(input, w_qkv, w_out);

    {
        dim3 grid(QKV_N / 256, ROWS / 128);
        gemm16<<<grid, 256, GEMM16_SMEM>>>(in16, wq16, b_qkv, qkv_ptr,
                                           ROWS, QKV_N, DIM);
    }

    rmsnorm_rope<<<ROWS, 256>>>(qkv_ptr, q_scale, k_scale);

    {
        dim3 grid(B_ * H_, N_ / 64);
        flash3<<<grid, 128, ATT_SMEM>>>();
    }

    {
        dim3 grid(DIM / 256, ROWS / 128);
        gemm16<<<grid, 256, GEMM16_SMEM>>>(a16, wo16, b_out, out,
                                           ROWS, DIM, DIM);
    }
}

// round 17
// speedup vs baseline: 1.4600x; 1.0163x over previous
#include <cuda_runtime.h>
#include <cuda_bf16.h>
#include <cuda_fp16.h>
#include <math.h>
#include <stdint.h>

// Problem constants
#define B_    2
#define N_    2048
#define DIM   1024
#define H_    16
#define HD    64
#define ROWS  (B_ * N_)     // 4096
#define QKV_N (3 * DIM)     // 3072

// ---------------------------------------------------------------------------
// Device scratch (allocation-free)
// ---------------------------------------------------------------------------
__device__ float g_qkv[(size_t)ROWS * QKV_N];
__device__ __half g_in16[(size_t)ROWS * DIM];
__device__ __half g_wq16[(size_t)DIM * QKV_N];      // [K][N]
__device__ __half g_wo16[(size_t)DIM * DIM];        // [K][N]
// head-major [b][h][n][64], all fp16 single
__device__ __half g_q16[(size_t)ROWS * DIM];
__device__ __half g_k16[(size_t)ROWS * DIM];
__device__ __half g_vh [(size_t)ROWS * DIM];
// attention output row-major [4096][1024], fp16
__device__ __half g_a16[(size_t)ROWS * DIM];
// RoPE cos/sin table [n][i] for i<32
__device__ float2 g_rope[(size_t)N_ * 32];

// ---------------------------------------------------------------------------
// PTX helpers
// ---------------------------------------------------------------------------
__device__ __forceinline__ uint32_t sm32(const void* p) {
    return (uint32_t)__cvta_generic_to_shared(p);
}
__device__ __forceinline__ void ldsm4(uint32_t r[4], uint32_t a) {
    asm volatile("ldmatrix.sync.aligned.m8n8.x4.shared.b16 {%0,%1,%2,%3},[%4];"
                 : "=r"(r[0]), "=r"(r[1]), "=r"(r[2]), "=r"(r[3]) : "r"(a));
}
__device__ __forceinline__ void ldsm4t(uint32_t r[4], uint32_t a) {
    asm volatile("ldmatrix.sync.aligned.m8n8.x4.trans.shared.b16 {%0,%1,%2,%3},[%4];"
                 : "=r"(r[0]), "=r"(r[1]), "=r"(r[2]), "=r"(r[3]) : "r"(a));
}
__device__ __forceinline__ void mma_f16(float d[4], const uint32_t a[4], const uint32_t b[2]) {
    asm volatile("mma.sync.aligned.m16n8k16.row.col.f32.f16.f16.f32 "
                 "{%0,%1,%2,%3},{%4,%5,%6,%7},{%8,%9},{%0,%1,%2,%3};"
                 : "+f"(d[0]), "+f"(d[1]), "+f"(d[2]), "+f"(d[3])
                 : "r"(a[0]), "r"(a[1]), "r"(a[2]), "r"(a[3]), "r"(b[0]), "r"(b[1]));
}
__device__ __forceinline__ void cpa16(void* dst, const void* src) {
    asm volatile("cp.async.cg.shared.global [%0],[%1],16;" :: "r"(sm32(dst)), "l"(src));
}
#define CP_COMMIT() asm volatile("cp.async.commit_group;")
#define CP_WAIT(n)  asm volatile("cp.async.wait_group %0;" :: "n"(n))

__device__ __forceinline__ uint32_t packh2(float a, float b) {
    __half2 h = __floats2half2_rn(a, b);
    return *(uint32_t*)&h;
}
__device__ __forceinline__ float ex2f(float x) {
    float r;
    asm("ex2.approx.ftz.f32 %0,%1;" : "=f"(r) : "f"(x));
    return r;
}

// ---------------------------------------------------------------------------
// Fused prepass: all fp32->fp16 conversions + RoPE table in ONE kernel.
// ---------------------------------------------------------------------------
#define PC0 (ROWS * DIM / 4)            // 1048576
#define PC1 (DIM * QKV_N / 4)           // 786432
#define PC2 (DIM * DIM / 4)             // 262144
#define PCT (PC0 + PC1 + PC2)           // 2097152
#define PTOT (PCT + N_ * 32)            // + 65536

__device__ __forceinline__ void conv4(const float* __restrict__ s,
                                      __half* __restrict__ d, int i) {
    float4 v = ((const float4*)s)[i];
    uint2 u = { packh2(v.x, v.y), packh2(v.z, v.w) };
    ((uint2*)d)[i] = u;
}

__global__ void prepass(const float* __restrict__ input,
                        const float* __restrict__ w_qkv,
                        const float* __restrict__ w_out) {
    int i = blockIdx.x * 256 + threadIdx.x;
    if (i < PC0) {
        conv4(input, g_in16, i);
    } else if (i < PC0 + PC1) {
        conv4(w_qkv, g_wq16, i - PC0);
    } else if (i < PCT) {
        conv4(w_out, g_wo16, i - PC0 - PC1);
    } else if (i < PTOT) {
        int idx = i - PCT;
        int n = idx >> 5, fi = idx & 31;
        double dinv = exp(-(double)(2 * fi) * (9.210340371976184 / 64.0));
        double da = fmod((double)n * dinv, 6.283185307179586476);
        g_rope[idx] = make_float2((float)cos(da), (float)sin(da));
    }
}

// ---------------------------------------------------------------------------
// Single-fp16 GEMM: C[M,N] = A[M,K] @ B[K,N] + bias
// 128x256 tile, BK=64, 3-stage cp.async, 256 threads, warp tile 64x64.
// ---------------------------------------------------------------------------
#define A16EL (128 * 72)
#define B16EL (64 * 264)
#define STG16 (A16EL + B16EL)
#define GEMM16_SMEM (3 * STG16 * 2)

__global__ void __launch_bounds__(256, 1) gemm16(
    const __half* __restrict__ A, const __half* __restrict__ B,
    const float* __restrict__ bias, float* __restrict__ C,
    int M, int N, int K)
{
    extern __shared__ __half smh[];

    const int tid = threadIdx.x, lane = tid & 31, warp = tid >> 5;
    const int bm = blockIdx.y * 128, bn = blockIdx.x * 256;
    const int wm = (warp >> 2) * 64, wn = (warp & 3) * 64;

    const int qd = lane >> 3, r8 = lane & 7;
    const int Arow = ((qd & 1) << 3) + r8, Acol = (qd & 2) << 2;

    float acc[4][8][4];
#pragma unroll
    for (int a = 0; a < 4; a++)
#pragma unroll
        for (int b = 0; b < 8; b++)
#pragma unroll
            for (int c = 0; c < 4; c++) acc[a][b][c] = 0.f;

    const int ar = tid >> 3,  ac = (tid & 7) * 8;
    const int br = tid >> 5,  bc = (tid & 31) * 8;
    const int nk = K / 64;

#define STAGE16(kt, s) do {                                                       \
    __half* st = smh + (s) * STG16;                                               \
    _Pragma("unroll")                                                             \
    for (int ii = 0; ii < 4; ii++) {                                              \
        int rr = ar + ii * 32;                                                    \
        cpa16(st + rr * 72 + ac, A + (size_t)(bm + rr) * K + (kt) * 64 + ac);     \
    }                                                                             \
    _Pragma("unroll")                                                             \
    for (int ii = 0; ii < 8; ii++) {                                              \
        int rr = br + ii * 8;                                                     \
        cpa16(st + A16EL + rr * 264 + bc,                                         \
              B + (size_t)((kt) * 64 + rr) * N + bn + bc);                        \
    }                                                                             \
    CP_COMMIT(); } while (0)

    STAGE16(0, 0);
    STAGE16(1, 1);
    CP_WAIT(1);
    __syncthreads();

    int buf = 0;
    for (int kt = 0; kt < nk; kt++) {
        int bufn = buf + 1 == 3 ? 0 : buf + 1;
        int bufp = bufn + 1 == 3 ? 0 : bufn + 1;
        if (kt + 2 < nk) STAGE16(kt + 2, bufp);

        const __half* st = smh + buf * STG16;
        const __half* Bp = st + A16EL;
#pragma unroll
        for (int ka = 0; ka < 4; ka++) {
            uint32_t af[4][4], bf[4][4];
#pragma unroll
            for (int ma = 0; ma < 4; ma++)
                ldsm4(af[ma], sm32(st + (wm + ma * 16 + Arow) * 72 + ka * 16 + Acol));
#pragma unroll
            for (int nb = 0; nb < 4; nb++)
                ldsm4t(bf[nb], sm32(Bp + (ka * 16 + Arow) * 264 + wn + nb * 16 + Acol));
#pragma unroll
            for (int ma = 0; ma < 4; ma++)
#pragma unroll
                for (int nb = 0; nb < 4; nb++) {
                    mma_f16(acc[ma][2 * nb],     af[ma], bf[nb]);
                    mma_f16(acc[ma][2 * nb + 1], af[ma], bf[nb] + 2);
                }
        }

        if (kt + 2 < nk) { CP_WAIT(1); } else { CP_WAIT(0); }
        __syncthreads();
        buf = bufn;
    }
#undef STAGE16

    const int gr = lane >> 2, tg = lane & 3;
#pragma unroll
    for (int ma = 0; ma < 4; ma++) {
        int row0 = bm + wm + ma * 16 + gr;
#pragma unroll
        for (int na = 0; na < 8; na++) {
            int col = bn + wn + na * 8 + 2 * tg;
            float2 v0 = { acc[ma][na][0] + bias[col], acc[ma][na][1] + bias[col + 1] };
            float2 v1 = { acc[ma][na][2] + bias[col], acc[ma][na][3] + bias[col + 1] };
            *(float2*)&C[(size_t)row0 * N + col]       = v0;
            *(float2*)&C[(size_t)(row0 + 8) * N + col] = v1;
        }
    }
}

// ---------------------------------------------------------------------------
// RMSNorm + RoPE; q, k, v all -> fp16 single (head-major).
// ---------------------------------------------------------------------------
__inline__ __device__ float warpsum(float v) {
#pragma unroll
    for (int o = 16; o; o >>= 1) v += __shfl_xor_sync(0xffffffffu, v, o);
    return v;
}

#define QSCALE (0.125f * 1.4426950408889634f)

__global__ void __launch_bounds__(256) rmsnorm_rope(
    const float* __restrict__ qkv,
    const float* __restrict__ q_scale, const float* __restrict__ k_scale)
{
    const int row = blockIdx.x;
    const int b = row >> 11, n = row & (N_ - 1);
    const float* qr = qkv + (size_t)row * QKV_N;
    const float* kr = qr + DIM;
    const float* vr = kr + DIM;
    const int tid = threadIdx.x;

    float sq = 0.f, sk = 0.f;
    for (int c = tid; c < DIM; c += 256) {
        float a = qr[c]; sq += a * a;
        float bb = kr[c]; sk += bb * bb;
    }
    sq = warpsum(sq);
    sk = warpsum(sk);
    __shared__ float sh[16];
    int w = tid >> 5, lane = tid & 31;
    if (lane == 0) { sh[w] = sq; sh[w + 8] = sk; }
    __syncthreads();
    if (tid == 0) {
        float t = 0.f, u = 0.f;
#pragma unroll
        for (int i = 0; i < 8; i++) { t += sh[i]; u += sh[i + 8]; }
        sh[0] = rsqrtf(t * (1.0f / DIM) + 1e-6f);
        sh[8] = rsqrtf(u * (1.0f / DIM) + 1e-6f);
    }
    __syncthreads();
    const float rq = sh[0], rk = sh[8];

    for (int p = tid; p < 512; p += 256) {
        int i = p & 31;
        int h = p >> 5;
        int c1 = h * 64 + i, c2 = c1 + 32;
        float2 cssn = g_rope[n * 32 + i];
        float cs = cssn.x, sn = cssn.y;

        size_t o1 = ((size_t)(b * 16 + h) * N_ + n) * 64 + i;
        size_t o2 = o1 + 32;

        float x1 = qr[c1] * rq * q_scale[c1];
        float x2 = qr[c2] * rq * q_scale[c2];
        g_q16[o1] = __float2half_rn((x1 * cs - x2 * sn) * QSCALE);
        g_q16[o2] = __float2half_rn((x2 * cs + x1 * sn) * QSCALE);

        float y1 = kr[c1] * rk * k_scale[c1];
        float y2 = kr[c2] * rk * k_scale[c2];
        g_k16[o1] = __float2half_rn(y1 * cs - y2 * sn);
        g_k16[o2] = __float2half_rn(y2 * cs + y1 * sn);
    }
    for (int c = tid; c < DIM; c += 256) {
        int h = c >> 6, d = c & 63;
        size_t o = ((size_t)(b * 16 + h) * N_ + n) * 64 + d;
        g_vh[o] = __float2half_rn(vr[c]);
    }
}

// ---------------------------------------------------------------------------
// Flash attention. 128 queries/block (4 warps x 32 queries = 2 M-halves),
// 128 threads, 2 CTAs/SM, 64-key tiles. K/V fragments shared across both
// M-halves (halves LDSM per MMA). S single fp16 MMA, exp2 softmax,
// P from acc regs, V fp16, output fp16.
// ---------------------------------------------------------------------------
#define QEL   (128 * 72)
#define KEL   (64 * 72)
#define KVST  (2 * KEL)             // K, V (fp16) per stage
#define ATT_SMEM ((QEL + 2 * KVST) * 2)   // 55296 B

__global__ void __launch_bounds__(128, 2) flash3()
{
    extern __shared__ __align__(1024) char smc[];
    __half* sQ  = (__half*)smc;
    __half* sKV = sQ + QEL;             // 2 stages of KVST elements

    const int tid = threadIdx.x, lane = tid & 31, warp = tid >> 5;
    const int bhid = blockIdx.x;
    const int b = bhid >> 4, h = bhid & 15;
    const size_t hb = (size_t)bhid * N_ * 64;
    const int q0 = blockIdx.y * 128;

#define FSTAGE(kt, s) do {                                                     \
    __half* st = sKV + (s) * KVST;                                             \
    _Pragma("unroll")                                                          \
    for (int i8 = 0; i8 < 4; i8++) {                                           \
        int cid = tid + i8 * 128;                                              \
        int rr = cid >> 3, cc = (cid & 7) * 8;                                 \
        size_t go = hb + (size_t)((kt) + rr) * 64 + cc;                        \
        int so = rr * 72 + cc;                                                 \
        cpa16(st + so,       g_k16 + go);                                      \
        cpa16(st + KEL + so, g_vh + go);                                       \
    }                                                                          \
    CP_COMMIT(); } while (0)

    FSTAGE(0, 0);

    // stage Q: 128 rows -> 1024 chunks, 128 threads -> 8 iterations
#pragma unroll
    for (int i = 0; i < 8; i++) {
        int cid = (i << 7) + tid;           // 0..1023
        int row = cid >> 3, col = (cid & 7) * 8;
        *(uint4*)(sQ + row * 72 + col) =
            *(const uint4*)(g_q16 + hb + (size_t)(q0 + row) * 64 + col);
    }
    CP_WAIT(0);
    __syncthreads();

    const int qd = lane >> 3, r8 = lane & 7;
    const int Arow = ((qd & 1) << 3) + r8, Acol = (qd & 2) << 2;
    const int Brow = ((qd & 2) << 2) + r8, Bcol = (qd & 1) << 3;
    const int gr = lane >> 2, tg = lane & 3;

    // hoist Q fragments for both M-halves (rows warp*16 and 64+warp*16)
    uint32_t qf[2][4][4];
#pragma unroll
    for (int mh = 0; mh < 2; mh++)
#pragma unroll
        for (int ka = 0; ka < 4; ka++)
            ldsm4(qf[mh][ka],
                  sm32(sQ + (mh * 64 + warp * 16 + Arow) * 72 + ka * 16 + Acol));

    float l[2][2] = {{0.f, 0.f}, {0.f, 0.f}};
    float o[2][8][4];
#pragma unroll
    for (int mh = 0; mh < 2; mh++)
#pragma unroll
        for (int a = 0; a < 8; a++)
#pragma unroll
            for (int c = 0; c < 4; c++) o[mh][a][c] = 0.f;

    for (int ti = 0; ti < N_ / 64; ti++) {
        const int buf = ti & 1;
        if (ti + 1 < N_ / 64) FSTAGE((ti + 1) * 64, buf ^ 1);

        __half* sKh = sKV + buf * KVST;
        __half* sVh = sKh + KEL;

        // S = q k^T for both M-halves; K fragments loaded ONCE per ka
        float s[2][8][4];
#pragma unroll
        for (int mh = 0; mh < 2; mh++)
#pragma unroll
            for (int a = 0; a < 8; a++)
#pragma unroll
                for (int c = 0; c < 4; c++) s[mh][a][c] = 0.f;

#pragma unroll
        for (int ka = 0; ka < 4; ka++) {
            uint32_t bh4[4][4];
#pragma unroll
            for (int nb = 0; nb < 4; nb++)
                ldsm4(bh4[nb], sm32(sKh + (nb * 16 + Brow) * 72 + ka * 16 + Bcol));
#pragma unroll
            for (int mh = 0; mh < 2; mh++)
#pragma unroll
                for (int nb = 0; nb < 4; nb++) {
                    mma_f16(s[mh][2 * nb],     qf[mh][ka], bh4[nb]);
                    mma_f16(s[mh][2 * nb + 1], qf[mh][ka], bh4[nb] + 2);
                }
        }

        // softmax numerator via exp2, accumulate l
#pragma unroll
        for (int mh = 0; mh < 2; mh++)
#pragma unroll
            for (int a = 0; a < 8; a++) {
                s[mh][a][0] = ex2f(s[mh][a][0]);
                s[mh][a][1] = ex2f(s[mh][a][1]);
                s[mh][a][2] = ex2f(s[mh][a][2]);
                s[mh][a][3] = ex2f(s[mh][a][3]);
                l[mh][0] += s[mh][a][0] + s[mh][a][1];
                l[mh][1] += s[mh][a][2] + s[mh][a][3];
            }

        // O += P V : V fragments loaded ONCE per ka, shared by both halves
#pragma unroll
        for (int ka = 0; ka < 4; ka++) {
            uint32_t vh4[4][4];
#pragma unroll
            for (int nb = 0; nb < 4; nb++)
                ldsm4t(vh4[nb], sm32(sVh + (ka * 16 + Arow) * 72 + nb * 16 + Acol));
#pragma unroll
            for (int mh = 0; mh < 2; mh++) {
                uint32_t pf[4];
                pf[0] = packh2(s[mh][2 * ka][0],     s[mh][2 * ka][1]);
                pf[1] = packh2(s[mh][2 * ka][2],     s[mh][2 * ka][3]);
                pf[2] = packh2(s[mh][2 * ka + 1][0], s[mh][2 * ka + 1][1]);
                pf[3] = packh2(s[mh][2 * ka + 1][2], s[mh][2 * ka + 1][3]);
#pragma unroll
                for (int nb = 0; nb < 4; nb++) {
                    mma_f16(o[mh][2 * nb],     pf, vh4[nb]);
                    mma_f16(o[mh][2 * nb + 1], pf, vh4[nb] + 2);
                }
            }
        }

        if (ti + 1 < N_ / 64) CP_WAIT(0);
        __syncthreads();
    }
#undef FSTAGE

    // reduce l across the 4 threads of each row group; epilogue per half
#pragma unroll
    for (int mh = 0; mh < 2; mh++) {
        float l0 = l[mh][0], l1 = l[mh][1];
        l0 += __shfl_xor_sync(0xffffffffu, l0, 1);
        l0 += __shfl_xor_sync(0xffffffffu, l0, 2);
        l1 += __shfl_xor_sync(0xffffffffu, l1, 1);
        l1 += __shfl_xor_sync(0xffffffffu, l1, 2);
        const float i0 = 1.f / l0, i1 = 1.f / l1;
        const int r0 = q0 + mh * 64 + warp * 16 + gr;
#pragma unroll
        for (int a = 0; a < 8; a++) {
            int col = h * 64 + a * 8 + 2 * tg;
            size_t off = ((size_t)(b * N_ + r0)) * DIM + col;
            *(uint32_t*)&g_a16[off] = packh2(o[mh][a][0] * i0, o[mh][a][1] * i0);
            off = ((size_t)(b * N_ + r0 + 8)) * DIM + col;
            *(uint32_t*)&g_a16[off] = packh2(o[mh][a][2] * i1, o[mh][a][3] * i1);
        }
    }
}

// ---------------------------------------------------------------------------
// Launch
// ---------------------------------------------------------------------------
extern "C" void kernel_launch(void* const* d_in, const int* in_sizes, int n_in,
                              void* d_out, int out_size)
{
    const float* input   = (const float*)d_in[0];
    const float* w_qkv   = (const float*)d_in[1];
    const float* b_qkv   = (const float*)d_in[2];
    const float* q_scale = (const float*)d_in[3];
    const float* k_scale = (const float*)d_in[4];
    const float* w_out   = (const float*)d_in[5];
    const float* b_out   = (const float*)d_in[6];
    float* out = (float*)d_out;

    float* qkv_ptr;
    __half *in16, *wq16, *wo16, *a16;
    cudaGetSymbolAddress((void**)&qkv_ptr, g_qkv);
    cudaGetSymbolAddress((void**)&in16, g_in16);
    cudaGetSymbolAddress((void**)&wq16, g_wq16);
    cudaGetSymbolAddress((void**)&wo16, g_wo16);
    cudaGetSymbolAddress((void**)&a16, g_a16);

    cudaFuncSetAttribute(gemm16, cudaFuncAttributeMaxDynamicSharedMemorySize, GEMM16_SMEM);
    cudaFuncSetAttribute(flash3, cudaFuncAttributeMaxDynamicSharedMemorySize, ATT_SMEM);

    // fused prepass (conversions + rope table), one launch
    prepass<<<(PTOT + 255) / 256, 256>>>(input, w_qkv, w_out);

    {
        dim3 grid(QKV_N / 256, ROWS / 128);
        gemm16<<<grid, 256, GEMM16_SMEM>>>(in16, wq16, b_qkv, qkv_ptr,
                                           ROWS, QKV_N, DIM);
    }

    rmsnorm_rope<<<ROWS, 256>>>(qkv_ptr, q_scale, k_scale);

    {
        dim3 grid(B_ * H_, N_ / 128);
        flash3<<<grid, 128, ATT_SMEM>>>();
    }

    {
        dim3 grid(DIM / 256, ROWS / 128);
        gemm16<<<grid, 256, GEMM16_SMEM>>>(a16, wo16, b_out, out,
                                           ROWS, DIM, DIM);
    }
}